// round 13
// baseline (speedup 1.0000x reference)
#include <cuda_runtime.h>
#include <cuda_bf16.h>
#include <math.h>

#define N_NODES 100000
#define N_EDGES 1600000
#define N_GRAPHS 2048
#define DIM 128
#define OUT_DIM 12
#define N_LAYERS 5
#define BN_EPS 1e-5f
#define TILE_ROWS 64
#define AS_STRIDE 132
#define WS_STRIDE 132
#define GEMM_BLOCKS 148
#define SCAN_B 1024
#define SCAN_NB ((N_NODES + SCAN_B - 1) / SCAN_B)   // 98

// ---------------- scratch (device globals; no allocation allowed) ----------------
// g_agg holds tf32 bit-patterns (GEMM A operand), written by agg_kernel.
__device__ __align__(16) unsigned g_agg[(size_t)N_NODES * DIM];
__device__ __align__(16) float g_z[(size_t)N_NODES * DIM];
__device__ __align__(16) float g_stats[2 * DIM];
__device__ __align__(16) float g_scale[DIM];
__device__ __align__(16) float g_shift[DIM];
__device__ __align__(16) float g_pool[(size_t)N_GRAPHS * DIM];
__device__ __align__(16) unsigned g_wcvt[(size_t)2 * N_LAYERS * DIM * DIM];
// CSR scratch
__device__ __align__(16) int g_deg[N_NODES];
__device__ __align__(16) int g_beg[N_NODES];
__device__ __align__(16) int g_cur[N_NODES];
__device__ __align__(16) int g_bsum[SCAN_NB];
__device__ __align__(16) int g_csrsrc[N_EDGES];

// ---------------- small utility kernels ----------------
__global__ void zero_kernel(float* p, int n4) {
    int i = blockIdx.x * blockDim.x + threadIdx.x;
    if (i < n4) ((float4*)p)[i] = make_float4(0.f, 0.f, 0.f, 0.f);
}

__global__ void zero_int_kernel(int* p, int n) {
    int i = blockIdx.x * blockDim.x + threadIdx.x;
    if (i < n) p[i] = 0;
}

// ---------------- CSR build ----------------
__global__ void count_kernel(const int* __restrict__ dst) {
    int i = blockIdx.x * blockDim.x + threadIdx.x;
    if (i < N_EDGES) atomicAdd(&g_deg[dst[i]], 1);
}

__global__ void scan_block_kernel() {
    __shared__ int sm[SCAN_B];
    int tid = threadIdx.x;
    int i = blockIdx.x * SCAN_B + tid;
    int v = (i < N_NODES) ? g_deg[i] : 0;
    sm[tid] = v;
    __syncthreads();
    for (int off = 1; off < SCAN_B; off <<= 1) {
        int t = (tid >= off) ? sm[tid - off] : 0;
        __syncthreads();
        sm[tid] += t;
        __syncthreads();
    }
    if (i < N_NODES) g_beg[i] = sm[tid] - v;
    if (tid == SCAN_B - 1) g_bsum[blockIdx.x] = sm[tid];
}

__global__ void scan_totals_kernel() {
    if (threadIdx.x == 0) {
        int run = 0;
        for (int i = 0; i < SCAN_NB; i++) { int t = g_bsum[i]; g_bsum[i] = run; run += t; }
    }
}

__global__ void scan_add_kernel() {
    int i = blockIdx.x * SCAN_B + threadIdx.x;
    if (i < N_NODES) {
        int b = g_beg[i] + g_bsum[blockIdx.x];
        g_beg[i] = b;
        g_cur[i] = b;
    }
}

__global__ void fill_kernel(const int* __restrict__ src, const int* __restrict__ dst) {
    int i = blockIdx.x * blockDim.x + threadIdx.x;
    if (i < N_EDGES) {
        int slot = atomicAdd(&g_cur[dst[i]], 1);
        g_csrsrc[slot] = src[i];
    }
}

// ---------------- tf32 helpers ----------------
__device__ __forceinline__ unsigned cvt_tf32(float x) {
    unsigned r;
    asm("cvt.rna.tf32.f32 %0, %1;" : "=r"(r) : "f"(x));
    return r;
}

__device__ __forceinline__ void mma_tf32(float* d, const unsigned* a, const unsigned* b) {
    asm volatile(
        "mma.sync.aligned.m16n8k8.row.col.f32.tf32.tf32.f32 "
        "{%0,%1,%2,%3}, {%4,%5,%6,%7}, {%8,%9}, {%0,%1,%2,%3};"
        : "+f"(d[0]), "+f"(d[1]), "+f"(d[2]), "+f"(d[3])
        : "r"(a[0]), "r"(a[1]), "r"(a[2]), "r"(a[3]), "r"(b[0]), "r"(b[1]));
}

__global__ void wcvt_kernel(const float* __restrict__ W1s, const float* __restrict__ W2s) {
    const int total = N_LAYERS * DIM * DIM;
    int i = blockIdx.x * blockDim.x + threadIdx.x;
    if (i < total) {
        g_wcvt[i] = cvt_tf32(W1s[i]);
        g_wcvt[total + i] = cvt_tf32(W2s[i]);
    }
}

// ---------------- fused aggregation (writes tf32 bits) ----------------
__device__ __forceinline__ float4 bnrelu4(float4 v, float4 sc, float4 sh, int raw) {
    if (!raw) {
        v.x = fmaxf(fmaf(v.x, sc.x, sh.x), 0.f);
        v.y = fmaxf(fmaf(v.y, sc.y, sh.y), 0.f);
        v.z = fmaxf(fmaf(v.z, sc.z, sh.z), 0.f);
        v.w = fmaxf(fmaf(v.w, sc.w, sh.w), 0.f);
    }
    return v;
}

// agg[n] = tf32(h[n] + sum_{e: dst=n} h[src]); h = bnrelu(z) on the fly.
// One warp per node; 8-way unrolled gather for MLP=8.
__global__ void agg_kernel(const float* __restrict__ z,
                           const float* __restrict__ scale,
                           const float* __restrict__ shift,
                           int raw,
                           unsigned* __restrict__ agg) {
    int node = (blockIdx.x * blockDim.x + threadIdx.x) >> 5;
    int lane = threadIdx.x & 31;
    if (node >= N_NODES) return;

    float4 sc = make_float4(1.f, 1.f, 1.f, 1.f);
    float4 sh = make_float4(0.f, 0.f, 0.f, 0.f);
    if (!raw) {
        sc = *(const float4*)(scale + lane * 4);
        sh = *(const float4*)(shift + lane * 4);
    }

    float4 acc = bnrelu4(*(const float4*)(z + (size_t)node * DIM + lane * 4), sc, sh, raw);

    const int beg = g_beg[node];
    const int d = g_deg[node];
    const size_t laneoff = lane * 4;

    for (int j0 = 0; j0 < d; j0 += 32) {
        int myidx = (j0 + lane < d) ? g_csrsrc[beg + j0 + lane] : 0;
        int cnt = min(32, d - j0);
        int k = 0;
        for (; k + 8 <= cnt; k += 8) {
            float4 v[8];
#pragma unroll
            for (int u = 0; u < 8; u++) {
                int s = __shfl_sync(0xffffffff, myidx, k + u);
                v[u] = *(const float4*)(z + (size_t)s * DIM + laneoff);
            }
#pragma unroll
            for (int u = 0; u < 8; u++) {
                float4 w = bnrelu4(v[u], sc, sh, raw);
                acc.x += w.x; acc.y += w.y; acc.z += w.z; acc.w += w.w;
            }
        }
        for (; k < cnt; k++) {
            int s = __shfl_sync(0xffffffff, myidx, k);
            float4 v = bnrelu4(*(const float4*)(z + (size_t)s * DIM + laneoff), sc, sh, raw);
            acc.x += v.x; acc.y += v.y; acc.z += v.z; acc.w += v.w;
        }
    }
    uint4 o;
    o.x = cvt_tf32(acc.x); o.y = cvt_tf32(acc.y);
    o.z = cvt_tf32(acc.z); o.w = cvt_tf32(acc.w);
    *(uint4*)(agg + (size_t)node * DIM + laneoff) = o;
}

// ---------------- fused 2-GEMM persistent kernel ----------------
// z = relu(A @ W1 + b1) @ W2 + b2, with fused column stats. A arrives as tf32
// bits; Tb stored as tf32 bits; mainloops are pure LDS+MMA (no cvt).
__global__ void __launch_bounds__(256, 1)
mlp_fused_tc(const unsigned* __restrict__ A,
             const unsigned* __restrict__ W1c,
             const unsigned* __restrict__ W2c,
             const float* __restrict__ b1,
             const float* __restrict__ b2,
             float* __restrict__ C,
             int M,
             float* __restrict__ stats,
             int ntiles) {
    extern __shared__ unsigned smu[];
    unsigned* W1s = smu;                                 // 128 x 132
    unsigned* W2s = smu + DIM * WS_STRIDE;               // 128 x 132
    unsigned* Ab = smu + 2 * DIM * WS_STRIDE;            // 64 x 132 (tf32 bits)
    unsigned* Tb = Ab + TILE_ROWS * AS_STRIDE;           // 64 x 132 (tf32 bits)
    const int tid = threadIdx.x;
    const int warp = tid >> 5;
    const int lane = tid & 31;

    for (int i = tid; i < DIM * DIM / 4; i += 256) {
        int r = i >> 5, c4 = (i & 31) * 4;
        uint4 v1 = *(const uint4*)(W1c + r * DIM + c4);
        uint4 v2 = *(const uint4*)(W2c + r * DIM + c4);
        unsigned* p1 = W1s + r * WS_STRIDE + c4;
        unsigned* p2 = W2s + r * WS_STRIDE + c4;
        p1[0] = v1.x; p1[1] = v1.y; p1[2] = v1.z; p1[3] = v1.w;
        p2[0] = v2.x; p2[1] = v2.y; p2[2] = v2.z; p2[3] = v2.w;
    }

    const int wm = (warp >> 2) * 32;
    const int wn = (warp & 3) * 32;
    const int lq = lane >> 2;
    const int lr = lane & 3;

    // prefetch first A tile
    int t = blockIdx.x;
    if (t < ntiles) {
        const unsigned* base = A + (size_t)t * TILE_ROWS * DIM;
        int maxrow = M - t * TILE_ROWS;
#pragma unroll
        for (int q = 0; q < 8; q++) {
            int idx = q * 256 + tid;
            int r = idx >> 5, c4 = (idx & 31) * 4;
            unsigned saddr = (unsigned)__cvta_generic_to_shared(Ab + r * AS_STRIDE + c4);
            const unsigned* g = base + (r < maxrow ? r : 0) * DIM + c4;
            int sz = (r < maxrow) ? 16 : 0;
            asm volatile("cp.async.cg.shared.global [%0], [%1], 16, %2;"
                         :: "r"(saddr), "l"(g), "r"(sz));
        }
    }
    asm volatile("cp.async.commit_group;");

    for (; t < ntiles; t += GEMM_BLOCKS) {
        asm volatile("cp.async.wait_group 0;");
        __syncthreads();   // A ready (W ready on first pass; prev Tb reads done)

        const int row0 = t * TILE_ROWS;

        // ---- mainloop 1: acc1 = A @ W1 ----
        float acc1[2][4][4];
#pragma unroll
        for (int i = 0; i < 2; i++)
#pragma unroll
            for (int j = 0; j < 4; j++)
#pragma unroll
                for (int q = 0; q < 4; q++) acc1[i][j][q] = 0.f;

#pragma unroll
        for (int ks = 0; ks < 16; ks++) {
            const int k0 = ks * 8;
            unsigned af[2][4];
#pragma unroll
            for (int i = 0; i < 2; i++) {
                const unsigned* base = Ab + (wm + i * 16 + lq) * AS_STRIDE + k0 + lr;
                af[i][0] = base[0];
                af[i][1] = base[8 * AS_STRIDE];
                af[i][2] = base[4];
                af[i][3] = base[8 * AS_STRIDE + 4];
            }
            unsigned bf[4][2];
#pragma unroll
            for (int j = 0; j < 4; j++) {
                const unsigned* base = W1s + (k0 + lr) * WS_STRIDE + wn + j * 8 + lq;
                bf[j][0] = base[0];
                bf[j][1] = base[4 * WS_STRIDE];
            }
#pragma unroll
            for (int i = 0; i < 2; i++)
#pragma unroll
                for (int j = 0; j < 4; j++) mma_tf32(acc1[i][j], af[i], bf[j]);
        }
        __syncthreads();   // all warps done reading Ab

        // prefetch next A tile into Ab (overlaps with epilogue1 + mainloop2)
        int nxt = t + GEMM_BLOCKS;
        if (nxt < ntiles) {
            const unsigned* base = A + (size_t)nxt * TILE_ROWS * DIM;
            int maxrow = M - nxt * TILE_ROWS;
#pragma unroll
            for (int q = 0; q < 8; q++) {
                int idx = q * 256 + tid;
                int r = idx >> 5, c4 = (idx & 31) * 4;
                unsigned saddr = (unsigned)__cvta_generic_to_shared(Ab + r * AS_STRIDE + c4);
                const unsigned* g = base + (r < maxrow ? r : 0) * DIM + c4;
                int sz = (r < maxrow) ? 16 : 0;
                asm volatile("cp.async.cg.shared.global [%0], [%1], 16, %2;"
                             :: "r"(saddr), "l"(g), "r"(sz));
            }
        }
        asm volatile("cp.async.commit_group;");

        // ---- epilogue 1: T = tf32(relu(acc1 + b1)) into smem ----
#pragma unroll
        for (int i = 0; i < 2; i++) {
#pragma unroll
            for (int j = 0; j < 4; j++) {
                int col = wn + j * 8 + lr * 2;
                float c0 = b1[col], c1 = b1[col + 1];
                int rl = wm + i * 16 + lq;
                uint2 v0, v1;
                v0.x = cvt_tf32(fmaxf(acc1[i][j][0] + c0, 0.f));
                v0.y = cvt_tf32(fmaxf(acc1[i][j][1] + c1, 0.f));
                v1.x = cvt_tf32(fmaxf(acc1[i][j][2] + c0, 0.f));
                v1.y = cvt_tf32(fmaxf(acc1[i][j][3] + c1, 0.f));
                *(uint2*)(Tb + rl * AS_STRIDE + col) = v0;
                *(uint2*)(Tb + (rl + 8) * AS_STRIDE + col) = v1;
            }
        }
        __syncthreads();   // T ready

        // ---- mainloop 2: acc2 = T @ W2 ----
        float acc2[2][4][4];
#pragma unroll
        for (int i = 0; i < 2; i++)
#pragma unroll
            for (int j = 0; j < 4; j++)
#pragma unroll
                for (int q = 0; q < 4; q++) acc2[i][j][q] = 0.f;

#pragma unroll
        for (int ks = 0; ks < 16; ks++) {
            const int k0 = ks * 8;
            unsigned af[2][4];
#pragma unroll
            for (int i = 0; i < 2; i++) {
                const unsigned* base = Tb + (wm + i * 16 + lq) * AS_STRIDE + k0 + lr;
                af[i][0] = base[0];
                af[i][1] = base[8 * AS_STRIDE];
                af[i][2] = base[4];
                af[i][3] = base[8 * AS_STRIDE + 4];
            }
            unsigned bf[4][2];
#pragma unroll
            for (int j = 0; j < 4; j++) {
                const unsigned* base = W2s + (k0 + lr) * WS_STRIDE + wn + j * 8 + lq;
                bf[j][0] = base[0];
                bf[j][1] = base[4 * WS_STRIDE];
            }
#pragma unroll
            for (int i = 0; i < 2; i++)
#pragma unroll
                for (int j = 0; j < 4; j++) mma_tf32(acc2[i][j], af[i], bf[j]);
        }

        // ---- epilogue 2: z = acc2 + b2, store + fused stats ----
        float csum[8], csq[8];
#pragma unroll
        for (int k = 0; k < 8; k++) { csum[k] = 0.f; csq[k] = 0.f; }

#pragma unroll
        for (int i = 0; i < 2; i++) {
#pragma unroll
            for (int j = 0; j < 4; j++) {
                int col = wn + j * 8 + lr * 2;
                float c0 = b2[col], c1 = b2[col + 1];
                int r0 = row0 + wm + i * 16 + lq;
                float2 v0, v1;
                v0.x = acc2[i][j][0] + c0; v0.y = acc2[i][j][1] + c1;
                v1.x = acc2[i][j][2] + c0; v1.y = acc2[i][j][3] + c1;
                bool ok0 = r0 < M, ok1 = r0 + 8 < M;
                if (ok0) *(float2*)(C + (size_t)r0 * DIM + col) = v0;
                if (ok1) *(float2*)(C + (size_t)(r0 + 8) * DIM + col) = v1;
                csum[j * 2]     += (ok0 ? v0.x : 0.f) + (ok1 ? v1.x : 0.f);
                csum[j * 2 + 1] += (ok0 ? v0.y : 0.f) + (ok1 ? v1.y : 0.f);
                csq[j * 2]      += (ok0 ? v0.x * v0.x : 0.f) + (ok1 ? v1.x * v1.x : 0.f);
                csq[j * 2 + 1]  += (ok0 ? v0.y * v0.y : 0.f) + (ok1 ? v1.y * v1.y : 0.f);
            }
        }
#pragma unroll
        for (int k = 0; k < 8; k++) {
#pragma unroll
            for (int off = 4; off < 32; off <<= 1) {
                csum[k] += __shfl_xor_sync(0xffffffff, csum[k], off);
                csq[k]  += __shfl_xor_sync(0xffffffff, csq[k], off);
            }
        }
        if (lq == 0) {
#pragma unroll
            for (int k = 0; k < 8; k++) {
                int col = wn + (k >> 1) * 8 + lr * 2 + (k & 1);
                atomicAdd(&stats[col], csum[k]);
                atomicAdd(&stats[DIM + col], csq[k]);
            }
        }
        __syncthreads();   // Tb reads done before next tile's epilogue1 rewrites it
    }
}

// ---------------- BatchNorm finalize ----------------
__global__ void bn_finalize(const float* __restrict__ stats,
                            const float* __restrict__ gamma,
                            const float* __restrict__ beta,
                            float* scale, float* shift) {
    int c = threadIdx.x;
    float mean = stats[c] / (float)N_NODES;
    float var = stats[DIM + c] / (float)N_NODES - mean * mean;
    float sc = gamma[c] * rsqrtf(var + BN_EPS);
    scale[c] = sc;
    shift[c] = beta[c] - mean * sc;
}

// ---------------- global_add_pool with fused bnrelu ----------------
__global__ void pool_kernel(const float* __restrict__ z,
                            const float* __restrict__ scale,
                            const float* __restrict__ shift,
                            const int* __restrict__ batch,
                            float* __restrict__ pool) {
    int node = (blockIdx.x * blockDim.x + threadIdx.x) >> 5;
    int lane = threadIdx.x & 31;
    if (node >= N_NODES) return;
    int b = batch[node];
    float4 v = *(const float4*)(z + (size_t)node * DIM + lane * 4);
    float4 sc = *(const float4*)(scale + lane * 4);
    float4 sh = *(const float4*)(shift + lane * 4);
    v.x = fmaxf(fmaf(v.x, sc.x, sh.x), 0.f);
    v.y = fmaxf(fmaf(v.y, sc.y, sh.y), 0.f);
    v.z = fmaxf(fmaf(v.z, sc.z, sh.z), 0.f);
    v.w = fmaxf(fmaf(v.w, sc.w, sh.w), 0.f);
    float* p = pool + (size_t)b * DIM + lane * 4;
    asm volatile("red.global.add.v4.f32 [%0], {%1,%2,%3,%4};"
                 :: "l"(p), "f"(v.x), "f"(v.y), "f"(v.z), "f"(v.w) : "memory");
}

// ---------------- head MLP ----------------
__global__ void head_kernel(const float* __restrict__ pool,
                            const float* __restrict__ Wh1, const float* __restrict__ bh1,
                            const float* __restrict__ Wh2, const float* __restrict__ bh2,
                            float* __restrict__ out) {
    __shared__ float row[DIM];
    __shared__ float hid[DIM];
    int g = blockIdx.x;
    int t = threadIdx.x;
    row[t] = pool[(size_t)g * DIM + t];
    __syncthreads();
    float acc = bh1[t];
    for (int k = 0; k < DIM; k++) acc = fmaf(row[k], Wh1[k * DIM + t], acc);
    hid[t] = fmaxf(acc, 0.f);
    __syncthreads();
    if (t < OUT_DIM) {
        float o = bh2[t];
        for (int k = 0; k < DIM; k++) o = fmaf(hid[k], Wh2[k * OUT_DIM + t], o);
        out[(size_t)g * OUT_DIM + t] = o;
    }
}

// ---------------- launch ----------------
extern "C" void kernel_launch(void* const* d_in, const int* in_sizes, int n_in,
                              void* d_out, int out_size) {
    const float* x     = (const float*)d_in[0];
    const int*   ei    = (const int*)d_in[1];
    const int*   batch = (const int*)d_in[2];
    const float* W1s = (const float*)d_in[3];
    const float* b1s = (const float*)d_in[4];
    const float* W2s = (const float*)d_in[5];
    const float* b2s = (const float*)d_in[6];
    const float* gammas = (const float*)d_in[7];
    const float* betas  = (const float*)d_in[8];
    const float* Wh1 = (const float*)d_in[9];
    const float* bh1 = (const float*)d_in[10];
    const float* Wh2 = (const float*)d_in[11];
    const float* bh2 = (const float*)d_in[12];
    float* out = (float*)d_out;

    float *zp, *statsp, *scalep, *shiftp, *poolp;
    unsigned *aggp, *wcp;
    int* degp;
    cudaGetSymbolAddress((void**)&aggp, g_agg);
    cudaGetSymbolAddress((void**)&zp, g_z);
    cudaGetSymbolAddress((void**)&statsp, g_stats);
    cudaGetSymbolAddress((void**)&scalep, g_scale);
    cudaGetSymbolAddress((void**)&shiftp, g_shift);
    cudaGetSymbolAddress((void**)&poolp, g_pool);
    cudaGetSymbolAddress((void**)&wcp, g_wcvt);
    cudaGetSymbolAddress((void**)&degp, g_deg);

    const int* src = ei;
    const int* dst = ei + N_EDGES;

    const int ntiles = (N_NODES + TILE_ROWS - 1) / TILE_ROWS;
    const int fusedSmem = (2 * DIM * WS_STRIDE + 2 * TILE_ROWS * AS_STRIDE) * sizeof(unsigned);
    const int wTotal = N_LAYERS * DIM * DIM;
    const int edgeB = (N_EDGES + 255) / 256;
    const int aggBlocks = (N_NODES * 32 + 255) / 256;
    cudaFuncSetAttribute(mlp_fused_tc, cudaFuncAttributeMaxDynamicSharedMemorySize, fusedSmem);

    // ---- one-time per call: weight convert + CSR build ----
    wcvt_kernel<<<(wTotal + 255) / 256, 256>>>(W1s, W2s);
    zero_int_kernel<<<(N_NODES + 255) / 256, 256>>>(degp, N_NODES);
    count_kernel<<<edgeB, 256>>>(dst);
    scan_block_kernel<<<SCAN_NB, SCAN_B>>>();
    scan_totals_kernel<<<1, 32>>>();
    scan_add_kernel<<<SCAN_NB, SCAN_B>>>();
    fill_kernel<<<edgeB, 256>>>(src, dst);

    for (int l = 0; l < N_LAYERS; l++) {
        const float* zin = (l == 0) ? x : zp;
        int raw = (l == 0) ? 1 : 0;
        // agg = tf32(h + sum_neighbors h), h = bnrelu(z_prev) on the fly
        agg_kernel<<<aggBlocks, 256>>>(zin, scalep, shiftp, raw, aggp);
        // z = relu(agg @ W1 + b1) @ W2 + b2, fused stats (T never hits gmem)
        zero_kernel<<<1, 64>>>(statsp, 64);
        mlp_fused_tc<<<GEMM_BLOCKS, 256, fusedSmem>>>(
            aggp,
            wcp + (size_t)l * DIM * DIM,
            wcp + (size_t)(wTotal + l * DIM * DIM),
            b1s + (size_t)l * DIM, b2s + (size_t)l * DIM,
            zp, N_NODES, statsp, ntiles);
        bn_finalize<<<1, DIM>>>(statsp, gammas + (size_t)l * DIM, betas + (size_t)l * DIM,
                                scalep, shiftp);
    }

    // global_add_pool of bnrelu(z_final)
    const int pool4 = N_GRAPHS * DIM / 4;
    zero_kernel<<<(pool4 + 255) / 256, 256>>>(poolp, pool4);
    pool_kernel<<<aggBlocks, 256>>>(zp, scalep, shiftp, batch, poolp);

    // head
    head_kernel<<<N_GRAPHS, DIM>>>(poolp, Wh1, bh1, Wh2, bh2, out);
}

// round 14
// speedup vs baseline: 1.0602x; 1.0602x over previous
#include <cuda_runtime.h>
#include <cuda_bf16.h>
#include <math.h>

#define N_NODES 100000
#define N_EDGES 1600000
#define N_GRAPHS 2048
#define DIM 128
#define OUT_DIM 12
#define N_LAYERS 5
#define BN_EPS 1e-5f
#define TILE_ROWS 64
#define AS_STRIDE 132
#define WS_STRIDE 132
#define GEMM_BLOCKS 148
#define SCAN_B 1024
#define SCAN_NB ((N_NODES + SCAN_B - 1) / SCAN_B)   // 98

// ---------------- scratch (device globals; no allocation allowed) ----------------
// g_agg holds tf32 bit-patterns (GEMM A operand), written by agg_kernel.
__device__ __align__(16) unsigned g_agg[(size_t)N_NODES * DIM];
__device__ __align__(16) float g_z[(size_t)N_NODES * DIM];
__device__ __align__(16) float g_stats[2 * DIM];
__device__ __align__(16) float g_scale[DIM];
__device__ __align__(16) float g_shift[DIM];
__device__ __align__(16) float g_pool[(size_t)N_GRAPHS * DIM];
__device__ __align__(16) unsigned g_wcvt[(size_t)2 * N_LAYERS * DIM * DIM];
// CSR scratch
__device__ __align__(16) int g_deg[N_NODES];
__device__ __align__(16) int g_beg[N_NODES];
__device__ __align__(16) int g_cur[N_NODES];
__device__ __align__(16) int g_bsum[SCAN_NB];
__device__ __align__(16) int g_csrsrc[N_EDGES];

// ---------------- small utility kernels ----------------
__global__ void zero_kernel(float* p, int n4) {
    int i = blockIdx.x * blockDim.x + threadIdx.x;
    if (i < n4) ((float4*)p)[i] = make_float4(0.f, 0.f, 0.f, 0.f);
}

__global__ void zero_int_kernel(int* p, int n) {
    int i = blockIdx.x * blockDim.x + threadIdx.x;
    if (i < n) p[i] = 0;
}

// ---------------- CSR build ----------------
__global__ void count_kernel(const int* __restrict__ dst) {
    int i = blockIdx.x * blockDim.x + threadIdx.x;
    if (i < N_EDGES) atomicAdd(&g_deg[dst[i]], 1);
}

__global__ void scan_block_kernel() {
    __shared__ int sm[SCAN_B];
    int tid = threadIdx.x;
    int i = blockIdx.x * SCAN_B + tid;
    int v = (i < N_NODES) ? g_deg[i] : 0;
    sm[tid] = v;
    __syncthreads();
    for (int off = 1; off < SCAN_B; off <<= 1) {
        int t = (tid >= off) ? sm[tid - off] : 0;
        __syncthreads();
        sm[tid] += t;
        __syncthreads();
    }
    if (i < N_NODES) g_beg[i] = sm[tid] - v;
    if (tid == SCAN_B - 1) g_bsum[blockIdx.x] = sm[tid];
}

__global__ void scan_totals_kernel() {
    if (threadIdx.x == 0) {
        int run = 0;
        for (int i = 0; i < SCAN_NB; i++) { int t = g_bsum[i]; g_bsum[i] = run; run += t; }
    }
}

__global__ void scan_add_kernel() {
    int i = blockIdx.x * SCAN_B + threadIdx.x;
    if (i < N_NODES) {
        int b = g_beg[i] + g_bsum[blockIdx.x];
        g_beg[i] = b;
        g_cur[i] = b;
    }
}

__global__ void fill_kernel(const int* __restrict__ src, const int* __restrict__ dst) {
    int i = blockIdx.x * blockDim.x + threadIdx.x;
    if (i < N_EDGES) {
        int slot = atomicAdd(&g_cur[dst[i]], 1);
        g_csrsrc[slot] = src[i];
    }
}

// ---------------- tf32 helpers ----------------
__device__ __forceinline__ unsigned cvt_tf32(float x) {
    unsigned r;
    asm("cvt.rna.tf32.f32 %0, %1;" : "=r"(r) : "f"(x));
    return r;
}

__device__ __forceinline__ void mma_tf32(float* d, const unsigned* a, const unsigned* b) {
    asm volatile(
        "mma.sync.aligned.m16n8k8.row.col.f32.tf32.tf32.f32 "
        "{%0,%1,%2,%3}, {%4,%5,%6,%7}, {%8,%9}, {%0,%1,%2,%3};"
        : "+f"(d[0]), "+f"(d[1]), "+f"(d[2]), "+f"(d[3])
        : "r"(a[0]), "r"(a[1]), "r"(a[2]), "r"(a[3]), "r"(b[0]), "r"(b[1]));
}

__global__ void wcvt_kernel(const float* __restrict__ W1s, const float* __restrict__ W2s) {
    const int total = N_LAYERS * DIM * DIM;
    int i = blockIdx.x * blockDim.x + threadIdx.x;
    if (i < total) {
        g_wcvt[i] = cvt_tf32(W1s[i]);
        g_wcvt[total + i] = cvt_tf32(W2s[i]);
    }
}

// ---------------- fused aggregation (R12 4-way gather; writes tf32 bits) --------
__device__ __forceinline__ float4 bnrelu4(float4 v, float4 sc, float4 sh, int raw) {
    if (!raw) {
        v.x = fmaxf(fmaf(v.x, sc.x, sh.x), 0.f);
        v.y = fmaxf(fmaf(v.y, sc.y, sh.y), 0.f);
        v.z = fmaxf(fmaf(v.z, sc.z, sh.z), 0.f);
        v.w = fmaxf(fmaf(v.w, sc.w, sh.w), 0.f);
    }
    return v;
}

__global__ void agg_kernel(const float* __restrict__ z,
                           const float* __restrict__ scale,
                           const float* __restrict__ shift,
                           int raw,
                           unsigned* __restrict__ agg) {
    int node = (blockIdx.x * blockDim.x + threadIdx.x) >> 5;
    int lane = threadIdx.x & 31;
    if (node >= N_NODES) return;

    float4 sc = make_float4(1.f, 1.f, 1.f, 1.f);
    float4 sh = make_float4(0.f, 0.f, 0.f, 0.f);
    if (!raw) {
        sc = *(const float4*)(scale + lane * 4);
        sh = *(const float4*)(shift + lane * 4);
    }

    float4 acc = bnrelu4(*(const float4*)(z + (size_t)node * DIM + lane * 4), sc, sh, raw);

    const int beg = g_beg[node];
    const int d = g_deg[node];
    const size_t laneoff = lane * 4;

    for (int j0 = 0; j0 < d; j0 += 32) {
        int myidx = (j0 + lane < d) ? g_csrsrc[beg + j0 + lane] : 0;
        int cnt = min(32, d - j0);
        int k = 0;
        for (; k + 4 <= cnt; k += 4) {
            int s0 = __shfl_sync(0xffffffff, myidx, k);
            int s1 = __shfl_sync(0xffffffff, myidx, k + 1);
            int s2 = __shfl_sync(0xffffffff, myidx, k + 2);
            int s3 = __shfl_sync(0xffffffff, myidx, k + 3);
            float4 v0 = *(const float4*)(z + (size_t)s0 * DIM + laneoff);
            float4 v1 = *(const float4*)(z + (size_t)s1 * DIM + laneoff);
            float4 v2 = *(const float4*)(z + (size_t)s2 * DIM + laneoff);
            float4 v3 = *(const float4*)(z + (size_t)s3 * DIM + laneoff);
            v0 = bnrelu4(v0, sc, sh, raw);
            v1 = bnrelu4(v1, sc, sh, raw);
            v2 = bnrelu4(v2, sc, sh, raw);
            v3 = bnrelu4(v3, sc, sh, raw);
            acc.x += v0.x + v1.x + v2.x + v3.x;
            acc.y += v0.y + v1.y + v2.y + v3.y;
            acc.z += v0.z + v1.z + v2.z + v3.z;
            acc.w += v0.w + v1.w + v2.w + v3.w;
        }
        for (; k < cnt; k++) {
            int s = __shfl_sync(0xffffffff, myidx, k);
            float4 v = bnrelu4(*(const float4*)(z + (size_t)s * DIM + laneoff), sc, sh, raw);
            acc.x += v.x; acc.y += v.y; acc.z += v.z; acc.w += v.w;
        }
    }
    uint4 o;
    o.x = cvt_tf32(acc.x); o.y = cvt_tf32(acc.y);
    o.z = cvt_tf32(acc.z); o.w = cvt_tf32(acc.w);
    *(uint4*)(agg + (size_t)node * DIM + laneoff) = o;
}

// ---------------- fused 2-GEMM persistent kernel ----------------
// z = relu(A @ W1 + b1) @ W2 + b2, with fused column stats. A arrives as tf32
// bits; Tb stored as tf32 bits; mainloops are pure LDS+MMA (no cvt).
__global__ void __launch_bounds__(256, 1)
mlp_fused_tc(const unsigned* __restrict__ A,
             const unsigned* __restrict__ W1c,
             const unsigned* __restrict__ W2c,
             const float* __restrict__ b1,
             const float* __restrict__ b2,
             float* __restrict__ C,
             int M,
             float* __restrict__ stats,
             int ntiles) {
    extern __shared__ unsigned smu[];
    unsigned* W1s = smu;                                 // 128 x 132
    unsigned* W2s = smu + DIM * WS_STRIDE;               // 128 x 132
    unsigned* Ab = smu + 2 * DIM * WS_STRIDE;            // 64 x 132 (tf32 bits)
    unsigned* Tb = Ab + TILE_ROWS * AS_STRIDE;           // 64 x 132 (tf32 bits)
    const int tid = threadIdx.x;
    const int warp = tid >> 5;
    const int lane = tid & 31;

    for (int i = tid; i < DIM * DIM / 4; i += 256) {
        int r = i >> 5, c4 = (i & 31) * 4;
        uint4 v1 = *(const uint4*)(W1c + r * DIM + c4);
        uint4 v2 = *(const uint4*)(W2c + r * DIM + c4);
        unsigned* p1 = W1s + r * WS_STRIDE + c4;
        unsigned* p2 = W2s + r * WS_STRIDE + c4;
        p1[0] = v1.x; p1[1] = v1.y; p1[2] = v1.z; p1[3] = v1.w;
        p2[0] = v2.x; p2[1] = v2.y; p2[2] = v2.z; p2[3] = v2.w;
    }

    const int wm = (warp >> 2) * 32;
    const int wn = (warp & 3) * 32;
    const int lq = lane >> 2;
    const int lr = lane & 3;

    // prefetch first A tile
    int t = blockIdx.x;
    if (t < ntiles) {
        const unsigned* base = A + (size_t)t * TILE_ROWS * DIM;
        int maxrow = M - t * TILE_ROWS;
#pragma unroll
        for (int q = 0; q < 8; q++) {
            int idx = q * 256 + tid;
            int r = idx >> 5, c4 = (idx & 31) * 4;
            unsigned saddr = (unsigned)__cvta_generic_to_shared(Ab + r * AS_STRIDE + c4);
            const unsigned* g = base + (r < maxrow ? r : 0) * DIM + c4;
            int sz = (r < maxrow) ? 16 : 0;
            asm volatile("cp.async.cg.shared.global [%0], [%1], 16, %2;"
                         :: "r"(saddr), "l"(g), "r"(sz));
        }
    }
    asm volatile("cp.async.commit_group;");

    for (; t < ntiles; t += GEMM_BLOCKS) {
        asm volatile("cp.async.wait_group 0;");
        __syncthreads();   // A ready (W ready on first pass; prev Tb reads done)

        const int row0 = t * TILE_ROWS;

        // ---- mainloop 1: acc1 = A @ W1 ----
        float acc1[2][4][4];
#pragma unroll
        for (int i = 0; i < 2; i++)
#pragma unroll
            for (int j = 0; j < 4; j++)
#pragma unroll
                for (int q = 0; q < 4; q++) acc1[i][j][q] = 0.f;

#pragma unroll
        for (int ks = 0; ks < 16; ks++) {
            const int k0 = ks * 8;
            unsigned af[2][4];
#pragma unroll
            for (int i = 0; i < 2; i++) {
                const unsigned* base = Ab + (wm + i * 16 + lq) * AS_STRIDE + k0 + lr;
                af[i][0] = base[0];
                af[i][1] = base[8 * AS_STRIDE];
                af[i][2] = base[4];
                af[i][3] = base[8 * AS_STRIDE + 4];
            }
            unsigned bf[4][2];
#pragma unroll
            for (int j = 0; j < 4; j++) {
                const unsigned* base = W1s + (k0 + lr) * WS_STRIDE + wn + j * 8 + lq;
                bf[j][0] = base[0];
                bf[j][1] = base[4 * WS_STRIDE];
            }
#pragma unroll
            for (int i = 0; i < 2; i++)
#pragma unroll
                for (int j = 0; j < 4; j++) mma_tf32(acc1[i][j], af[i], bf[j]);
        }
        __syncthreads();   // all warps done reading Ab

        // prefetch next A tile into Ab (overlaps with epilogue1 + mainloop2)
        int nxt = t + GEMM_BLOCKS;
        if (nxt < ntiles) {
            const unsigned* base = A + (size_t)nxt * TILE_ROWS * DIM;
            int maxrow = M - nxt * TILE_ROWS;
#pragma unroll
            for (int q = 0; q < 8; q++) {
                int idx = q * 256 + tid;
                int r = idx >> 5, c4 = (idx & 31) * 4;
                unsigned saddr = (unsigned)__cvta_generic_to_shared(Ab + r * AS_STRIDE + c4);
                const unsigned* g = base + (r < maxrow ? r : 0) * DIM + c4;
                int sz = (r < maxrow) ? 16 : 0;
                asm volatile("cp.async.cg.shared.global [%0], [%1], 16, %2;"
                             :: "r"(saddr), "l"(g), "r"(sz));
            }
        }
        asm volatile("cp.async.commit_group;");

        // ---- epilogue 1: T = tf32(relu(acc1 + b1)) into smem ----
#pragma unroll
        for (int i = 0; i < 2; i++) {
#pragma unroll
            for (int j = 0; j < 4; j++) {
                int col = wn + j * 8 + lr * 2;
                float c0 = b1[col], c1 = b1[col + 1];
                int rl = wm + i * 16 + lq;
                uint2 v0, v1;
                v0.x = cvt_tf32(fmaxf(acc1[i][j][0] + c0, 0.f));
                v0.y = cvt_tf32(fmaxf(acc1[i][j][1] + c1, 0.f));
                v1.x = cvt_tf32(fmaxf(acc1[i][j][2] + c0, 0.f));
                v1.y = cvt_tf32(fmaxf(acc1[i][j][3] + c1, 0.f));
                *(uint2*)(Tb + rl * AS_STRIDE + col) = v0;
                *(uint2*)(Tb + (rl + 8) * AS_STRIDE + col) = v1;
            }
        }
        __syncthreads();   // T ready

        // ---- mainloop 2: acc2 = T @ W2 ----
        float acc2[2][4][4];
#pragma unroll
        for (int i = 0; i < 2; i++)
#pragma unroll
            for (int j = 0; j < 4; j++)
#pragma unroll
                for (int q = 0; q < 4; q++) acc2[i][j][q] = 0.f;

#pragma unroll
        for (int ks = 0; ks < 16; ks++) {
            const int k0 = ks * 8;
            unsigned af[2][4];
#pragma unroll
            for (int i = 0; i < 2; i++) {
                const unsigned* base = Tb + (wm + i * 16 + lq) * AS_STRIDE + k0 + lr;
                af[i][0] = base[0];
                af[i][1] = base[8 * AS_STRIDE];
                af[i][2] = base[4];
                af[i][3] = base[8 * AS_STRIDE + 4];
            }
            unsigned bf[4][2];
#pragma unroll
            for (int j = 0; j < 4; j++) {
                const unsigned* base = W2s + (k0 + lr) * WS_STRIDE + wn + j * 8 + lq;
                bf[j][0] = base[0];
                bf[j][1] = base[4 * WS_STRIDE];
            }
#pragma unroll
            for (int i = 0; i < 2; i++)
#pragma unroll
                for (int j = 0; j < 4; j++) mma_tf32(acc2[i][j], af[i], bf[j]);
        }

        // ---- epilogue 2: z = acc2 + b2, store + fused stats ----
        float csum[8], csq[8];
#pragma unroll
        for (int k = 0; k < 8; k++) { csum[k] = 0.f; csq[k] = 0.f; }

#pragma unroll
        for (int i = 0; i < 2; i++) {
#pragma unroll
            for (int j = 0; j < 4; j++) {
                int col = wn + j * 8 + lr * 2;
                float c0 = b2[col], c1 = b2[col + 1];
                int r0 = row0 + wm + i * 16 + lq;
                float2 v0, v1;
                v0.x = acc2[i][j][0] + c0; v0.y = acc2[i][j][1] + c1;
                v1.x = acc2[i][j][2] + c0; v1.y = acc2[i][j][3] + c1;
                bool ok0 = r0 < M, ok1 = r0 + 8 < M;
                if (ok0) *(float2*)(C + (size_t)r0 * DIM + col) = v0;
                if (ok1) *(float2*)(C + (size_t)(r0 + 8) * DIM + col) = v1;
                csum[j * 2]     += (ok0 ? v0.x : 0.f) + (ok1 ? v1.x : 0.f);
                csum[j * 2 + 1] += (ok0 ? v0.y : 0.f) + (ok1 ? v1.y : 0.f);
                csq[j * 2]      += (ok0 ? v0.x * v0.x : 0.f) + (ok1 ? v1.x * v1.x : 0.f);
                csq[j * 2 + 1]  += (ok0 ? v0.y * v0.y : 0.f) + (ok1 ? v1.y * v1.y : 0.f);
            }
        }
#pragma unroll
        for (int k = 0; k < 8; k++) {
#pragma unroll
            for (int off = 4; off < 32; off <<= 1) {
                csum[k] += __shfl_xor_sync(0xffffffff, csum[k], off);
                csq[k]  += __shfl_xor_sync(0xffffffff, csq[k], off);
            }
        }
        if (lq == 0) {
#pragma unroll
            for (int k = 0; k < 8; k++) {
                int col = wn + (k >> 1) * 8 + lr * 2 + (k & 1);
                atomicAdd(&stats[col], csum[k]);
                atomicAdd(&stats[DIM + col], csq[k]);
            }
        }
        __syncthreads();   // Tb reads done before next tile's epilogue1 rewrites it
    }
}

// ---------------- BatchNorm finalize ----------------
__global__ void bn_finalize(const float* __restrict__ stats,
                            const float* __restrict__ gamma,
                            const float* __restrict__ beta,
                            float* scale, float* shift) {
    int c = threadIdx.x;
    float mean = stats[c] / (float)N_NODES;
    float var = stats[DIM + c] / (float)N_NODES - mean * mean;
    float sc = gamma[c] * rsqrtf(var + BN_EPS);
    scale[c] = sc;
    shift[c] = beta[c] - mean * sc;
}

// ---------------- global_add_pool with fused bnrelu ----------------
__global__ void pool_kernel(const float* __restrict__ z,
                            const float* __restrict__ scale,
                            const float* __restrict__ shift,
                            const int* __restrict__ batch,
                            float* __restrict__ pool) {
    int node = (blockIdx.x * blockDim.x + threadIdx.x) >> 5;
    int lane = threadIdx.x & 31;
    if (node >= N_NODES) return;
    int b = batch[node];
    float4 v = *(const float4*)(z + (size_t)node * DIM + lane * 4);
    float4 sc = *(const float4*)(scale + lane * 4);
    float4 sh = *(const float4*)(shift + lane * 4);
    v.x = fmaxf(fmaf(v.x, sc.x, sh.x), 0.f);
    v.y = fmaxf(fmaf(v.y, sc.y, sh.y), 0.f);
    v.z = fmaxf(fmaf(v.z, sc.z, sh.z), 0.f);
    v.w = fmaxf(fmaf(v.w, sc.w, sh.w), 0.f);
    float* p = pool + (size_t)b * DIM + lane * 4;
    asm volatile("red.global.add.v4.f32 [%0], {%1,%2,%3,%4};"
                 :: "l"(p), "f"(v.x), "f"(v.y), "f"(v.z), "f"(v.w) : "memory");
}

// ---------------- head MLP ----------------
__global__ void head_kernel(const float* __restrict__ pool,
                            const float* __restrict__ Wh1, const float* __restrict__ bh1,
                            const float* __restrict__ Wh2, const float* __restrict__ bh2,
                            float* __restrict__ out) {
    __shared__ float row[DIM];
    __shared__ float hid[DIM];
    int g = blockIdx.x;
    int t = threadIdx.x;
    row[t] = pool[(size_t)g * DIM + t];
    __syncthreads();
    float acc = bh1[t];
    for (int k = 0; k < DIM; k++) acc = fmaf(row[k], Wh1[k * DIM + t], acc);
    hid[t] = fmaxf(acc, 0.f);
    __syncthreads();
    if (t < OUT_DIM) {
        float o = bh2[t];
        for (int k = 0; k < DIM; k++) o = fmaf(hid[k], Wh2[k * OUT_DIM + t], o);
        out[(size_t)g * OUT_DIM + t] = o;
    }
}

// ---------------- launch ----------------
extern "C" void kernel_launch(void* const* d_in, const int* in_sizes, int n_in,
                              void* d_out, int out_size) {
    const float* x     = (const float*)d_in[0];
    const int*   ei    = (const int*)d_in[1];
    const int*   batch = (const int*)d_in[2];
    const float* W1s = (const float*)d_in[3];
    const float* b1s = (const float*)d_in[4];
    const float* W2s = (const float*)d_in[5];
    const float* b2s = (const float*)d_in[6];
    const float* gammas = (const float*)d_in[7];
    const float* betas  = (const float*)d_in[8];
    const float* Wh1 = (const float*)d_in[9];
    const float* bh1 = (const float*)d_in[10];
    const float* Wh2 = (const float*)d_in[11];
    const float* bh2 = (const float*)d_in[12];
    float* out = (float*)d_out;

    float *zp, *statsp, *scalep, *shiftp, *poolp;
    unsigned *aggp, *wcp;
    int* degp;
    cudaGetSymbolAddress((void**)&aggp, g_agg);
    cudaGetSymbolAddress((void**)&zp, g_z);
    cudaGetSymbolAddress((void**)&statsp, g_stats);
    cudaGetSymbolAddress((void**)&scalep, g_scale);
    cudaGetSymbolAddress((void**)&shiftp, g_shift);
    cudaGetSymbolAddress((void**)&poolp, g_pool);
    cudaGetSymbolAddress((void**)&wcp, g_wcvt);
    cudaGetSymbolAddress((void**)&degp, g_deg);

    const int* src = ei;
    const int* dst = ei + N_EDGES;

    const int ntiles = (N_NODES + TILE_ROWS - 1) / TILE_ROWS;
    const int fusedSmem = (2 * DIM * WS_STRIDE + 2 * TILE_ROWS * AS_STRIDE) * sizeof(unsigned);
    const int wTotal = N_LAYERS * DIM * DIM;
    const int edgeB = (N_EDGES + 255) / 256;
    const int aggBlocks = (N_NODES * 32 + 255) / 256;
    cudaFuncSetAttribute(mlp_fused_tc, cudaFuncAttributeMaxDynamicSharedMemorySize, fusedSmem);

    // ---- one-time per call: weight convert + CSR build ----
    wcvt_kernel<<<(wTotal + 255) / 256, 256>>>(W1s, W2s);
    zero_int_kernel<<<(N_NODES + 255) / 256, 256>>>(degp, N_NODES);
    count_kernel<<<edgeB, 256>>>(dst);
    scan_block_kernel<<<SCAN_NB, SCAN_B>>>();
    scan_totals_kernel<<<1, 32>>>();
    scan_add_kernel<<<SCAN_NB, SCAN_B>>>();
    fill_kernel<<<edgeB, 256>>>(src, dst);

    for (int l = 0; l < N_LAYERS; l++) {
        const float* zin = (l == 0) ? x : zp;
        int raw = (l == 0) ? 1 : 0;
        // agg = tf32(h + sum_neighbors h), h = bnrelu(z_prev) on the fly
        agg_kernel<<<aggBlocks, 256>>>(zin, scalep, shiftp, raw, aggp);
        // z = relu(agg @ W1 + b1) @ W2 + b2, fused stats (T never hits gmem)
        zero_kernel<<<1, 64>>>(statsp, 64);
        mlp_fused_tc<<<GEMM_BLOCKS, 256, fusedSmem>>>(
            aggp,
            wcp + (size_t)l * DIM * DIM,
            wcp + (size_t)(wTotal + l * DIM * DIM),
            b1s + (size_t)l * DIM, b2s + (size_t)l * DIM,
            zp, N_NODES, statsp, ntiles);
        bn_finalize<<<1, DIM>>>(statsp, gammas + (size_t)l * DIM, betas + (size_t)l * DIM,
                                scalep, shiftp);
    }

    // global_add_pool of bnrelu(z_final)
    const int pool4 = N_GRAPHS * DIM / 4;
    zero_kernel<<<(pool4 + 255) / 256, 256>>>(poolp, pool4);
    pool_kernel<<<aggBlocks, 256>>>(zp, scalep, shiftp, batch, poolp);

    // head
    head_kernel<<<N_GRAPHS, DIM>>>(poolp, Wh1, bh1, Wh2, bh2, out);
}

// round 15
// speedup vs baseline: 1.0902x; 1.0283x over previous
#include <cuda_runtime.h>
#include <cuda_fp16.h>
#include <math.h>

#define N_NODES 100000
#define N_EDGES 1600000
#define N_GRAPHS 2048
#define DIM 128
#define OUT_DIM 12
#define N_LAYERS 5
#define BN_EPS 1e-5f
#define TILE_ROWS 64
#define AS_STRIDE 132
#define WS_STRIDE 132
#define GEMM_BLOCKS 148
#define SCAN_B 1024
#define SCAN_NB ((N_NODES + SCAN_B - 1) / SCAN_B)   // 98

// ---------------- scratch (device globals; no allocation allowed) ----------------
// g_agg holds tf32 bit-patterns (GEMM A operand); g_z holds fp16 activations.
__device__ __align__(16) unsigned g_agg[(size_t)N_NODES * DIM];
__device__ __align__(16) __half g_z[(size_t)N_NODES * DIM];
__device__ __align__(16) float g_stats[N_LAYERS * 2 * DIM];
__device__ __align__(16) float g_scale[DIM];
__device__ __align__(16) float g_shift[DIM];
__device__ __align__(16) float g_pool[(size_t)N_GRAPHS * DIM];
__device__ __align__(16) unsigned g_wcvt[(size_t)2 * N_LAYERS * DIM * DIM];
// CSR scratch
__device__ __align__(16) int g_deg[N_NODES];
__device__ __align__(16) int g_beg[N_NODES];
__device__ __align__(16) int g_cur[N_NODES];
__device__ __align__(16) int g_bsum[SCAN_NB];
__device__ __align__(16) int g_csrsrc[N_EDGES];

// ---------------- small utility kernels ----------------
__global__ void zero_kernel(float* p, int n4) {
    int i = blockIdx.x * blockDim.x + threadIdx.x;
    if (i < n4) ((float4*)p)[i] = make_float4(0.f, 0.f, 0.f, 0.f);
}

__global__ void zero_int_kernel(int* p, int n) {
    int i = blockIdx.x * blockDim.x + threadIdx.x;
    if (i < n) p[i] = 0;
}

// ---------------- CSR build ----------------
__global__ void count_kernel(const int* __restrict__ dst) {
    int i = blockIdx.x * blockDim.x + threadIdx.x;
    if (i < N_EDGES) atomicAdd(&g_deg[dst[i]], 1);
}

__global__ void scan_block_kernel() {
    __shared__ int sm[SCAN_B];
    int tid = threadIdx.x;
    int i = blockIdx.x * SCAN_B + tid;
    int v = (i < N_NODES) ? g_deg[i] : 0;
    sm[tid] = v;
    __syncthreads();
    for (int off = 1; off < SCAN_B; off <<= 1) {
        int t = (tid >= off) ? sm[tid - off] : 0;
        __syncthreads();
        sm[tid] += t;
        __syncthreads();
    }
    if (i < N_NODES) g_beg[i] = sm[tid] - v;
    if (tid == SCAN_B - 1) g_bsum[blockIdx.x] = sm[tid];
}

__global__ void scan_totals_kernel() {
    if (threadIdx.x == 0) {
        int run = 0;
        for (int i = 0; i < SCAN_NB; i++) { int t = g_bsum[i]; g_bsum[i] = run; run += t; }
    }
}

__global__ void scan_add_kernel() {
    int i = blockIdx.x * SCAN_B + threadIdx.x;
    if (i < N_NODES) {
        int b = g_beg[i] + g_bsum[blockIdx.x];
        g_beg[i] = b;
        g_cur[i] = b;
    }
}

__global__ void fill_kernel(const int* __restrict__ src, const int* __restrict__ dst) {
    int i = blockIdx.x * blockDim.x + threadIdx.x;
    if (i < N_EDGES) {
        int slot = atomicAdd(&g_cur[dst[i]], 1);
        g_csrsrc[slot] = src[i];
    }
}

// ---------------- tf32 helpers ----------------
__device__ __forceinline__ unsigned cvt_tf32(float x) {
    unsigned r;
    asm("cvt.rna.tf32.f32 %0, %1;" : "=r"(r) : "f"(x));
    return r;
}

__device__ __forceinline__ void mma_tf32(float* d, const unsigned* a, const unsigned* b) {
    asm volatile(
        "mma.sync.aligned.m16n8k8.row.col.f32.tf32.tf32.f32 "
        "{%0,%1,%2,%3}, {%4,%5,%6,%7}, {%8,%9}, {%0,%1,%2,%3};"
        : "+f"(d[0]), "+f"(d[1]), "+f"(d[2]), "+f"(d[3])
        : "r"(a[0]), "r"(a[1]), "r"(a[2]), "r"(a[3]), "r"(b[0]), "r"(b[1]));
}

__global__ void wcvt_kernel(const float* __restrict__ W1s, const float* __restrict__ W2s) {
    const int total = N_LAYERS * DIM * DIM;
    int i = blockIdx.x * blockDim.x + threadIdx.x;
    if (i < total) {
        g_wcvt[i] = cvt_tf32(W1s[i]);
        g_wcvt[total + i] = cvt_tf32(W2s[i]);
    }
}

// ---------------- fused aggregation (4-way gather; fp16 z; writes tf32 bits) ----
__device__ __forceinline__ float4 bnrelu4(float4 v, float4 sc, float4 sh, int raw) {
    if (!raw) {
        v.x = fmaxf(fmaf(v.x, sc.x, sh.x), 0.f);
        v.y = fmaxf(fmaf(v.y, sc.y, sh.y), 0.f);
        v.z = fmaxf(fmaf(v.z, sc.z, sh.z), 0.f);
        v.w = fmaxf(fmaf(v.w, sc.w, sh.w), 0.f);
    }
    return v;
}

// load 4 consecutive half values as float4
__device__ __forceinline__ float4 ldh4(const __half* p) {
    uint2 u = *(const uint2*)p;
    __half2 h01 = *(__half2*)&u.x;
    __half2 h23 = *(__half2*)&u.y;
    float2 f01 = __half22float2(h01);
    float2 f23 = __half22float2(h23);
    return make_float4(f01.x, f01.y, f23.x, f23.y);
}

// agg[n] = tf32(h[n] + sum_{e: dst=n} h[src]); h = bnrelu(z) on the fly.
// raw=1 (layer 0): h read from fp32 x; else from fp16 z.
__global__ void agg_kernel(const float* __restrict__ xf,
                           const __half* __restrict__ zh,
                           const float* __restrict__ scale,
                           const float* __restrict__ shift,
                           int raw,
                           unsigned* __restrict__ agg) {
    int node = (blockIdx.x * blockDim.x + threadIdx.x) >> 5;
    int lane = threadIdx.x & 31;
    if (node >= N_NODES) return;

    float4 sc = make_float4(1.f, 1.f, 1.f, 1.f);
    float4 sh = make_float4(0.f, 0.f, 0.f, 0.f);
    if (!raw) {
        sc = *(const float4*)(scale + lane * 4);
        sh = *(const float4*)(shift + lane * 4);
    }

    const size_t laneoff = lane * 4;
    float4 self = raw ? *(const float4*)(xf + (size_t)node * DIM + laneoff)
                      : ldh4(zh + (size_t)node * DIM + laneoff);
    float4 acc = bnrelu4(self, sc, sh, raw);

    const int beg = g_beg[node];
    const int d = g_deg[node];

    for (int j0 = 0; j0 < d; j0 += 32) {
        int myidx = (j0 + lane < d) ? g_csrsrc[beg + j0 + lane] : 0;
        int cnt = min(32, d - j0);
        int k = 0;
        for (; k + 4 <= cnt; k += 4) {
            int s0 = __shfl_sync(0xffffffff, myidx, k);
            int s1 = __shfl_sync(0xffffffff, myidx, k + 1);
            int s2 = __shfl_sync(0xffffffff, myidx, k + 2);
            int s3 = __shfl_sync(0xffffffff, myidx, k + 3);
            float4 v0, v1, v2, v3;
            if (raw) {
                v0 = *(const float4*)(xf + (size_t)s0 * DIM + laneoff);
                v1 = *(const float4*)(xf + (size_t)s1 * DIM + laneoff);
                v2 = *(const float4*)(xf + (size_t)s2 * DIM + laneoff);
                v3 = *(const float4*)(xf + (size_t)s3 * DIM + laneoff);
            } else {
                v0 = ldh4(zh + (size_t)s0 * DIM + laneoff);
                v1 = ldh4(zh + (size_t)s1 * DIM + laneoff);
                v2 = ldh4(zh + (size_t)s2 * DIM + laneoff);
                v3 = ldh4(zh + (size_t)s3 * DIM + laneoff);
            }
            v0 = bnrelu4(v0, sc, sh, raw);
            v1 = bnrelu4(v1, sc, sh, raw);
            v2 = bnrelu4(v2, sc, sh, raw);
            v3 = bnrelu4(v3, sc, sh, raw);
            acc.x += v0.x + v1.x + v2.x + v3.x;
            acc.y += v0.y + v1.y + v2.y + v3.y;
            acc.z += v0.z + v1.z + v2.z + v3.z;
            acc.w += v0.w + v1.w + v2.w + v3.w;
        }
        for (; k < cnt; k++) {
            int s = __shfl_sync(0xffffffff, myidx, k);
            float4 v = raw ? *(const float4*)(xf + (size_t)s * DIM + laneoff)
                           : ldh4(zh + (size_t)s * DIM + laneoff);
            v = bnrelu4(v, sc, sh, raw);
            acc.x += v.x; acc.y += v.y; acc.z += v.z; acc.w += v.w;
        }
    }
    uint4 o;
    o.x = cvt_tf32(acc.x); o.y = cvt_tf32(acc.y);
    o.z = cvt_tf32(acc.z); o.w = cvt_tf32(acc.w);
    *(uint4*)(agg + (size_t)node * DIM + laneoff) = o;
}

// ---------------- fused 2-GEMM persistent kernel ----------------
// z(fp16) = relu(A @ W1 + b1) @ W2 + b2, with fused fp32 column stats.
__global__ void __launch_bounds__(256, 1)
mlp_fused_tc(const unsigned* __restrict__ A,
             const unsigned* __restrict__ W1c,
             const unsigned* __restrict__ W2c,
             const float* __restrict__ b1,
             const float* __restrict__ b2,
             __half* __restrict__ C,
             int M,
             float* __restrict__ stats,
             int ntiles) {
    extern __shared__ unsigned smu[];
    unsigned* W1s = smu;                                 // 128 x 132
    unsigned* W2s = smu + DIM * WS_STRIDE;               // 128 x 132
    unsigned* Ab = smu + 2 * DIM * WS_STRIDE;            // 64 x 132 (tf32 bits)
    unsigned* Tb = Ab + TILE_ROWS * AS_STRIDE;           // 64 x 132 (tf32 bits)
    const int tid = threadIdx.x;
    const int warp = tid >> 5;
    const int lane = tid & 31;

    for (int i = tid; i < DIM * DIM / 4; i += 256) {
        int r = i >> 5, c4 = (i & 31) * 4;
        uint4 v1 = *(const uint4*)(W1c + r * DIM + c4);
        uint4 v2 = *(const uint4*)(W2c + r * DIM + c4);
        unsigned* p1 = W1s + r * WS_STRIDE + c4;
        unsigned* p2 = W2s + r * WS_STRIDE + c4;
        p1[0] = v1.x; p1[1] = v1.y; p1[2] = v1.z; p1[3] = v1.w;
        p2[0] = v2.x; p2[1] = v2.y; p2[2] = v2.z; p2[3] = v2.w;
    }

    const int wm = (warp >> 2) * 32;
    const int wn = (warp & 3) * 32;
    const int lq = lane >> 2;
    const int lr = lane & 3;

    // prefetch first A tile
    int t = blockIdx.x;
    if (t < ntiles) {
        const unsigned* base = A + (size_t)t * TILE_ROWS * DIM;
        int maxrow = M - t * TILE_ROWS;
#pragma unroll
        for (int q = 0; q < 8; q++) {
            int idx = q * 256 + tid;
            int r = idx >> 5, c4 = (idx & 31) * 4;
            unsigned saddr = (unsigned)__cvta_generic_to_shared(Ab + r * AS_STRIDE + c4);
            const unsigned* g = base + (r < maxrow ? r : 0) * DIM + c4;
            int sz = (r < maxrow) ? 16 : 0;
            asm volatile("cp.async.cg.shared.global [%0], [%1], 16, %2;"
                         :: "r"(saddr), "l"(g), "r"(sz));
        }
    }
    asm volatile("cp.async.commit_group;");

    for (; t < ntiles; t += GEMM_BLOCKS) {
        asm volatile("cp.async.wait_group 0;");
        __syncthreads();   // A ready (W ready on first pass; prev Tb reads done)

        const int row0 = t * TILE_ROWS;

        // ---- mainloop 1: acc1 = A @ W1 ----
        float acc1[2][4][4];
#pragma unroll
        for (int i = 0; i < 2; i++)
#pragma unroll
            for (int j = 0; j < 4; j++)
#pragma unroll
                for (int q = 0; q < 4; q++) acc1[i][j][q] = 0.f;

#pragma unroll
        for (int ks = 0; ks < 16; ks++) {
            const int k0 = ks * 8;
            unsigned af[2][4];
#pragma unroll
            for (int i = 0; i < 2; i++) {
                const unsigned* base = Ab + (wm + i * 16 + lq) * AS_STRIDE + k0 + lr;
                af[i][0] = base[0];
                af[i][1] = base[8 * AS_STRIDE];
                af[i][2] = base[4];
                af[i][3] = base[8 * AS_STRIDE + 4];
            }
            unsigned bf[4][2];
#pragma unroll
            for (int j = 0; j < 4; j++) {
                const unsigned* base = W1s + (k0 + lr) * WS_STRIDE + wn + j * 8 + lq;
                bf[j][0] = base[0];
                bf[j][1] = base[4 * WS_STRIDE];
            }
#pragma unroll
            for (int i = 0; i < 2; i++)
#pragma unroll
                for (int j = 0; j < 4; j++) mma_tf32(acc1[i][j], af[i], bf[j]);
        }
        __syncthreads();   // all warps done reading Ab

        // prefetch next A tile into Ab (overlaps with epilogue1 + mainloop2)
        int nxt = t + GEMM_BLOCKS;
        if (nxt < ntiles) {
            const unsigned* base = A + (size_t)nxt * TILE_ROWS * DIM;
            int maxrow = M - nxt * TILE_ROWS;
#pragma unroll
            for (int q = 0; q < 8; q++) {
                int idx = q * 256 + tid;
                int r = idx >> 5, c4 = (idx & 31) * 4;
                unsigned saddr = (unsigned)__cvta_generic_to_shared(Ab + r * AS_STRIDE + c4);
                const unsigned* g = base + (r < maxrow ? r : 0) * DIM + c4;
                int sz = (r < maxrow) ? 16 : 0;
                asm volatile("cp.async.cg.shared.global [%0], [%1], 16, %2;"
                             :: "r"(saddr), "l"(g), "r"(sz));
            }
        }
        asm volatile("cp.async.commit_group;");

        // ---- epilogue 1: T = tf32(relu(acc1 + b1)) into smem ----
#pragma unroll
        for (int i = 0; i < 2; i++) {
#pragma unroll
            for (int j = 0; j < 4; j++) {
                int col = wn + j * 8 + lr * 2;
                float c0 = b1[col], c1 = b1[col + 1];
                int rl = wm + i * 16 + lq;
                uint2 v0, v1;
                v0.x = cvt_tf32(fmaxf(acc1[i][j][0] + c0, 0.f));
                v0.y = cvt_tf32(fmaxf(acc1[i][j][1] + c1, 0.f));
                v1.x = cvt_tf32(fmaxf(acc1[i][j][2] + c0, 0.f));
                v1.y = cvt_tf32(fmaxf(acc1[i][j][3] + c1, 0.f));
                *(uint2*)(Tb + rl * AS_STRIDE + col) = v0;
                *(uint2*)(Tb + (rl + 8) * AS_STRIDE + col) = v1;
            }
        }
        __syncthreads();   // T ready

        // ---- mainloop 2: acc2 = T @ W2 ----
        float acc2[2][4][4];
#pragma unroll
        for (int i = 0; i < 2; i++)
#pragma unroll
            for (int j = 0; j < 4; j++)
#pragma unroll
                for (int q = 0; q < 4; q++) acc2[i][j][q] = 0.f;

#pragma unroll
        for (int ks = 0; ks < 16; ks++) {
            const int k0 = ks * 8;
            unsigned af[2][4];
#pragma unroll
            for (int i = 0; i < 2; i++) {
                const unsigned* base = Tb + (wm + i * 16 + lq) * AS_STRIDE + k0 + lr;
                af[i][0] = base[0];
                af[i][1] = base[8 * AS_STRIDE];
                af[i][2] = base[4];
                af[i][3] = base[8 * AS_STRIDE + 4];
            }
            unsigned bf[4][2];
#pragma unroll
            for (int j = 0; j < 4; j++) {
                const unsigned* base = W2s + (k0 + lr) * WS_STRIDE + wn + j * 8 + lq;
                bf[j][0] = base[0];
                bf[j][1] = base[4 * WS_STRIDE];
            }
#pragma unroll
            for (int i = 0; i < 2; i++)
#pragma unroll
                for (int j = 0; j < 4; j++) mma_tf32(acc2[i][j], af[i], bf[j]);
        }

        // ---- epilogue 2: z = fp16(acc2 + b2), store + fused fp32 stats ----
        float csum[8], csq[8];
#pragma unroll
        for (int k = 0; k < 8; k++) { csum[k] = 0.f; csq[k] = 0.f; }

#pragma unroll
        for (int i = 0; i < 2; i++) {
#pragma unroll
            for (int j = 0; j < 4; j++) {
                int col = wn + j * 8 + lr * 2;
                float c0 = b2[col], c1 = b2[col + 1];
                int r0 = row0 + wm + i * 16 + lq;
                float2 v0, v1;
                v0.x = acc2[i][j][0] + c0; v0.y = acc2[i][j][1] + c1;
                v1.x = acc2[i][j][2] + c0; v1.y = acc2[i][j][3] + c1;
                bool ok0 = r0 < M, ok1 = r0 + 8 < M;
                if (ok0) *(__half2*)(C + (size_t)r0 * DIM + col) = __floats2half2_rn(v0.x, v0.y);
                if (ok1) *(__half2*)(C + (size_t)(r0 + 8) * DIM + col) = __floats2half2_rn(v1.x, v1.y);
                csum[j * 2]     += (ok0 ? v0.x : 0.f) + (ok1 ? v1.x : 0.f);
                csum[j * 2 + 1] += (ok0 ? v0.y : 0.f) + (ok1 ? v1.y : 0.f);
                csq[j * 2]      += (ok0 ? v0.x * v0.x : 0.f) + (ok1 ? v1.x * v1.x : 0.f);
                csq[j * 2 + 1]  += (ok0 ? v0.y * v0.y : 0.f) + (ok1 ? v1.y * v1.y : 0.f);
            }
        }
#pragma unroll
        for (int k = 0; k < 8; k++) {
#pragma unroll
            for (int off = 4; off < 32; off <<= 1) {
                csum[k] += __shfl_xor_sync(0xffffffff, csum[k], off);
                csq[k]  += __shfl_xor_sync(0xffffffff, csq[k], off);
            }
        }
        if (lq == 0) {
#pragma unroll
            for (int k = 0; k < 8; k++) {
                int col = wn + (k >> 1) * 8 + lr * 2 + (k & 1);
                atomicAdd(&stats[col], csum[k]);
                atomicAdd(&stats[DIM + col], csq[k]);
            }
        }
        __syncthreads();   // Tb reads done before next tile's epilogue1 rewrites it
    }
}

// ---------------- BatchNorm finalize ----------------
__global__ void bn_finalize(const float* __restrict__ stats,
                            const float* __restrict__ gamma,
                            const float* __restrict__ beta,
                            float* scale, float* shift) {
    int c = threadIdx.x;
    float mean = stats[c] / (float)N_NODES;
    float var = stats[DIM + c] / (float)N_NODES - mean * mean;
    float sc = gamma[c] * rsqrtf(var + BN_EPS);
    scale[c] = sc;
    shift[c] = beta[c] - mean * sc;
}

// ---------------- global_add_pool with fused bnrelu (fp16 z) ----------------
__global__ void pool_kernel(const __half* __restrict__ z,
                            const float* __restrict__ scale,
                            const float* __restrict__ shift,
                            const int* __restrict__ batch,
                            float* __restrict__ pool) {
    int node = (blockIdx.x * blockDim.x + threadIdx.x) >> 5;
    int lane = threadIdx.x & 31;
    if (node >= N_NODES) return;
    int b = batch[node];
    float4 v = ldh4(z + (size_t)node * DIM + lane * 4);
    float4 sc = *(const float4*)(scale + lane * 4);
    float4 sh = *(const float4*)(shift + lane * 4);
    v.x = fmaxf(fmaf(v.x, sc.x, sh.x), 0.f);
    v.y = fmaxf(fmaf(v.y, sc.y, sh.y), 0.f);
    v.z = fmaxf(fmaf(v.z, sc.z, sh.z), 0.f);
    v.w = fmaxf(fmaf(v.w, sc.w, sh.w), 0.f);
    float* p = pool + (size_t)b * DIM + lane * 4;
    asm volatile("red.global.add.v4.f32 [%0], {%1,%2,%3,%4};"
                 :: "l"(p), "f"(v.x), "f"(v.y), "f"(v.z), "f"(v.w) : "memory");
}

// ---------------- head MLP ----------------
__global__ void head_kernel(const float* __restrict__ pool,
                            const float* __restrict__ Wh1, const float* __restrict__ bh1,
                            const float* __restrict__ Wh2, const float* __restrict__ bh2,
                            float* __restrict__ out) {
    __shared__ float row[DIM];
    __shared__ float hid[DIM];
    int g = blockIdx.x;
    int t = threadIdx.x;
    row[t] = pool[(size_t)g * DIM + t];
    __syncthreads();
    float acc = bh1[t];
    for (int k = 0; k < DIM; k++) acc = fmaf(row[k], Wh1[k * DIM + t], acc);
    hid[t] = fmaxf(acc, 0.f);
    __syncthreads();
    if (t < OUT_DIM) {
        float o = bh2[t];
        for (int k = 0; k < DIM; k++) o = fmaf(hid[k], Wh2[k * OUT_DIM + t], o);
        out[(size_t)g * OUT_DIM + t] = o;
    }
}

// ---------------- launch ----------------
extern "C" void kernel_launch(void* const* d_in, const int* in_sizes, int n_in,
                              void* d_out, int out_size) {
    const float* x     = (const float*)d_in[0];
    const int*   ei    = (const int*)d_in[1];
    const int*   batch = (const int*)d_in[2];
    const float* W1s = (const float*)d_in[3];
    const float* b1s = (const float*)d_in[4];
    const float* W2s = (const float*)d_in[5];
    const float* b2s = (const float*)d_in[6];
    const float* gammas = (const float*)d_in[7];
    const float* betas  = (const float*)d_in[8];
    const float* Wh1 = (const float*)d_in[9];
    const float* bh1 = (const float*)d_in[10];
    const float* Wh2 = (const float*)d_in[11];
    const float* bh2 = (const float*)d_in[12];
    float* out = (float*)d_out;

    float *statsp, *scalep, *shiftp, *poolp;
    unsigned *aggp, *wcp;
    __half* zp;
    int* degp;
    cudaGetSymbolAddress((void**)&aggp, g_agg);
    cudaGetSymbolAddress((void**)&zp, g_z);
    cudaGetSymbolAddress((void**)&statsp, g_stats);
    cudaGetSymbolAddress((void**)&scalep, g_scale);
    cudaGetSymbolAddress((void**)&shiftp, g_shift);
    cudaGetSymbolAddress((void**)&poolp, g_pool);
    cudaGetSymbolAddress((void**)&wcp, g_wcvt);
    cudaGetSymbolAddress((void**)&degp, g_deg);

    const int* src = ei;
    const int* dst = ei + N_EDGES;

    const int ntiles = (N_NODES + TILE_ROWS - 1) / TILE_ROWS;
    const int fusedSmem = (2 * DIM * WS_STRIDE + 2 * TILE_ROWS * AS_STRIDE) * sizeof(unsigned);
    const int wTotal = N_LAYERS * DIM * DIM;
    const int edgeB = (N_EDGES + 255) / 256;
    const int aggBlocks = (N_NODES * 32 + 255) / 256;
    cudaFuncSetAttribute(mlp_fused_tc, cudaFuncAttributeMaxDynamicSharedMemorySize, fusedSmem);

    // ---- one-time per call: weight convert + stats zero + CSR build ----
    wcvt_kernel<<<(wTotal + 255) / 256, 256>>>(W1s, W2s);
    zero_kernel<<<1, N_LAYERS * 2 * DIM / 4>>>(statsp, N_LAYERS * 2 * DIM / 4);
    zero_int_kernel<<<(N_NODES + 255) / 256, 256>>>(degp, N_NODES);
    count_kernel<<<edgeB, 256>>>(dst);
    scan_block_kernel<<<SCAN_NB, SCAN_B>>>();
    scan_totals_kernel<<<1, 32>>>();
    scan_add_kernel<<<SCAN_NB, SCAN_B>>>();
    fill_kernel<<<edgeB, 256>>>(src, dst);

    for (int l = 0; l < N_LAYERS; l++) {
        int raw = (l == 0) ? 1 : 0;
        float* lstats = statsp + (size_t)l * 2 * DIM;
        // agg = tf32(h + sum_neighbors h), h = bnrelu(z_prev) on the fly
        agg_kernel<<<aggBlocks, 256>>>(x, zp, scalep, shiftp, raw, aggp);
        // z = fp16(relu(agg @ W1 + b1) @ W2 + b2), fused stats
        mlp_fused_tc<<<GEMM_BLOCKS, 256, fusedSmem>>>(
            aggp,
            wcp + (size_t)l * DIM * DIM,
            wcp + (size_t)(wTotal + l * DIM * DIM),
            b1s + (size_t)l * DIM, b2s + (size_t)l * DIM,
            zp, N_NODES, lstats, ntiles);
        bn_finalize<<<1, DIM>>>(lstats, gammas + (size_t)l * DIM, betas + (size_t)l * DIM,
                                scalep, shiftp);
    }

    // global_add_pool of bnrelu(z_final)
    const int pool4 = N_GRAPHS * DIM / 4;
    zero_kernel<<<(pool4 + 255) / 256, 256>>>(poolp, pool4);
    pool_kernel<<<aggBlocks, 256>>>(zp, scalep, shiftp, batch, poolp);

    // head
    head_kernel<<<N_GRAPHS, DIM>>>(poolp, Wh1, bh1, Wh2, bh2, out);
}

// round 17
// speedup vs baseline: 1.2147x; 1.1142x over previous
#include <cuda_runtime.h>
#include <cuda_fp16.h>
#include <math.h>

#define N_NODES 100000
#define N_EDGES 1600000
#define N_GRAPHS 2048
#define DIM 128
#define OUT_DIM 12
#define N_LAYERS 5
#define BN_EPS 1e-5f
#define TILE_ROWS 64
#define AS_H 136          // Ab/Tb stride in halves (272B, 16B-aligned rows)
#define WPS 132           // packed-W stride in half2 units
#define GEMM_BLOCKS 148
#define SCAN_B 1024
#define SCAN_NB ((N_NODES + SCAN_B - 1) / SCAN_B)   // 98

// ---------------- scratch (device globals; no allocation allowed) ----------------
__device__ __align__(16) __half g_agg[(size_t)N_NODES * DIM];   // fp16 GEMM A operand
__device__ __align__(16) __half g_z[(size_t)N_NODES * DIM];     // fp16 activations
__device__ __align__(16) float g_stats[N_LAYERS * 2 * DIM];
__device__ __align__(16) float g_scale[DIM];
__device__ __align__(16) float g_shift[DIM];
__device__ __align__(16) float g_pool[(size_t)N_GRAPHS * DIM];
// packed fp16 weights: per layer, per matrix: [64 k2][128 n] half2 (k-paired)
__device__ __align__(16) unsigned g_wpack[(size_t)2 * N_LAYERS * 64 * DIM];
// CSR scratch
__device__ __align__(16) int g_deg[N_NODES];
__device__ __align__(16) int g_beg[N_NODES];
__device__ __align__(16) int g_cur[N_NODES];
__device__ __align__(16) int g_bsum[SCAN_NB];
__device__ __align__(16) int g_csrsrc[N_EDGES];

// ---------------- small utility kernels ----------------
__global__ void zero_kernel(float* p, int n4) {
    int i = blockIdx.x * blockDim.x + threadIdx.x;
    if (i < n4) ((float4*)p)[i] = make_float4(0.f, 0.f, 0.f, 0.f);
}

__global__ void zero_int_kernel(int* p, int n) {
    int i = blockIdx.x * blockDim.x + threadIdx.x;
    if (i < n) p[i] = 0;
}

// ---------------- CSR build ----------------
__global__ void count_kernel(const int* __restrict__ dst) {
    int i = blockIdx.x * blockDim.x + threadIdx.x;
    if (i < N_EDGES) atomicAdd(&g_deg[dst[i]], 1);
}

__global__ void scan_block_kernel() {
    __shared__ int sm[SCAN_B];
    int tid = threadIdx.x;
    int i = blockIdx.x * SCAN_B + tid;
    int v = (i < N_NODES) ? g_deg[i] : 0;
    sm[tid] = v;
    __syncthreads();
    for (int off = 1; off < SCAN_B; off <<= 1) {
        int t = (tid >= off) ? sm[tid - off] : 0;
        __syncthreads();
        sm[tid] += t;
        __syncthreads();
    }
    if (i < N_NODES) g_beg[i] = sm[tid] - v;
    if (tid == SCAN_B - 1) g_bsum[blockIdx.x] = sm[tid];
}

__global__ void scan_totals_kernel() {
    if (threadIdx.x == 0) {
        int run = 0;
        for (int i = 0; i < SCAN_NB; i++) { int t = g_bsum[i]; g_bsum[i] = run; run += t; }
    }
}

__global__ void scan_add_kernel() {
    int i = blockIdx.x * SCAN_B + threadIdx.x;
    if (i < N_NODES) {
        int b = g_beg[i] + g_bsum[blockIdx.x];
        g_beg[i] = b;
        g_cur[i] = b;
    }
}

__global__ void fill_kernel(const int* __restrict__ src, const int* __restrict__ dst) {
    int i = blockIdx.x * blockDim.x + threadIdx.x;
    if (i < N_EDGES) {
        int slot = atomicAdd(&g_cur[dst[i]], 1);
        g_csrsrc[slot] = src[i];
    }
}

// ---------------- weight pack: fp16 k-paired fragments ----------------
// Wp[l][k2][n] = half2(W[2*k2][n], W[2*k2+1][n])
__global__ void wpack_kernel(const float* __restrict__ W1s, const float* __restrict__ W2s) {
    const int per = 64 * DIM;                 // per matrix per layer
    const int total = N_LAYERS * per;
    int i = blockIdx.x * blockDim.x + threadIdx.x;
    if (i >= total) return;
    int l = i / per, rem = i % per;
    int k2 = rem / DIM, n = rem % DIM;
    size_t base = (size_t)l * DIM * DIM + (size_t)(2 * k2) * DIM + n;
    __half2 h1 = __floats2half2_rn(W1s[base], W1s[base + DIM]);
    __half2 h2 = __floats2half2_rn(W2s[base], W2s[base + DIM]);
    g_wpack[(size_t)l * per + rem] = *(unsigned*)&h1;
    g_wpack[(size_t)(N_LAYERS + l) * per + rem] = *(unsigned*)&h2;
}

// ---------------- fp16 mma helper ----------------
__device__ __forceinline__ void mma_f16(float* d, const unsigned* a, const unsigned* b) {
    asm volatile(
        "mma.sync.aligned.m16n8k16.row.col.f32.f16.f16.f32 "
        "{%0,%1,%2,%3}, {%4,%5,%6,%7}, {%8,%9}, {%0,%1,%2,%3};"
        : "+f"(d[0]), "+f"(d[1]), "+f"(d[2]), "+f"(d[3])
        : "r"(a[0]), "r"(a[1]), "r"(a[2]), "r"(a[3]), "r"(b[0]), "r"(b[1]));
}

// ---------------- fused aggregation (4-way gather; fp16 z; writes fp16) ----------
__device__ __forceinline__ float4 bnrelu4(float4 v, float4 sc, float4 sh, int raw) {
    if (!raw) {
        v.x = fmaxf(fmaf(v.x, sc.x, sh.x), 0.f);
        v.y = fmaxf(fmaf(v.y, sc.y, sh.y), 0.f);
        v.z = fmaxf(fmaf(v.z, sc.z, sh.z), 0.f);
        v.w = fmaxf(fmaf(v.w, sc.w, sh.w), 0.f);
    }
    return v;
}

__device__ __forceinline__ float4 ldh4(const __half* p) {
    uint2 u = *(const uint2*)p;
    __half2 h01 = *(__half2*)&u.x;
    __half2 h23 = *(__half2*)&u.y;
    float2 f01 = __half22float2(h01);
    float2 f23 = __half22float2(h23);
    return make_float4(f01.x, f01.y, f23.x, f23.y);
}

__global__ void agg_kernel(const float* __restrict__ xf,
                           const __half* __restrict__ zh,
                           const float* __restrict__ scale,
                           const float* __restrict__ shift,
                           int raw,
                           __half* __restrict__ agg) {
    int node = (blockIdx.x * blockDim.x + threadIdx.x) >> 5;
    int lane = threadIdx.x & 31;
    if (node >= N_NODES) return;

    float4 sc = make_float4(1.f, 1.f, 1.f, 1.f);
    float4 sh = make_float4(0.f, 0.f, 0.f, 0.f);
    if (!raw) {
        sc = *(const float4*)(scale + lane * 4);
        sh = *(const float4*)(shift + lane * 4);
    }

    const size_t laneoff = lane * 4;
    float4 self = raw ? *(const float4*)(xf + (size_t)node * DIM + laneoff)
                      : ldh4(zh + (size_t)node * DIM + laneoff);
    float4 acc = bnrelu4(self, sc, sh, raw);

    const int beg = g_beg[node];
    const int d = g_deg[node];

    for (int j0 = 0; j0 < d; j0 += 32) {
        int myidx = (j0 + lane < d) ? g_csrsrc[beg + j0 + lane] : 0;
        int cnt = min(32, d - j0);
        int k = 0;
        for (; k + 4 <= cnt; k += 4) {
            int s0 = __shfl_sync(0xffffffff, myidx, k);
            int s1 = __shfl_sync(0xffffffff, myidx, k + 1);
            int s2 = __shfl_sync(0xffffffff, myidx, k + 2);
            int s3 = __shfl_sync(0xffffffff, myidx, k + 3);
            float4 v0, v1, v2, v3;
            if (raw) {
                v0 = *(const float4*)(xf + (size_t)s0 * DIM + laneoff);
                v1 = *(const float4*)(xf + (size_t)s1 * DIM + laneoff);
                v2 = *(const float4*)(xf + (size_t)s2 * DIM + laneoff);
                v3 = *(const float4*)(xf + (size_t)s3 * DIM + laneoff);
            } else {
                v0 = ldh4(zh + (size_t)s0 * DIM + laneoff);
                v1 = ldh4(zh + (size_t)s1 * DIM + laneoff);
                v2 = ldh4(zh + (size_t)s2 * DIM + laneoff);
                v3 = ldh4(zh + (size_t)s3 * DIM + laneoff);
            }
            v0 = bnrelu4(v0, sc, sh, raw);
            v1 = bnrelu4(v1, sc, sh, raw);
            v2 = bnrelu4(v2, sc, sh, raw);
            v3 = bnrelu4(v3, sc, sh, raw);
            acc.x += v0.x + v1.x + v2.x + v3.x;
            acc.y += v0.y + v1.y + v2.y + v3.y;
            acc.z += v0.z + v1.z + v2.z + v3.z;
            acc.w += v0.w + v1.w + v2.w + v3.w;
        }
        for (; k < cnt; k++) {
            int s = __shfl_sync(0xffffffff, myidx, k);
            float4 v = raw ? *(const float4*)(xf + (size_t)s * DIM + laneoff)
                           : ldh4(zh + (size_t)s * DIM + laneoff);
            v = bnrelu4(v, sc, sh, raw);
            acc.x += v.x; acc.y += v.y; acc.z += v.z; acc.w += v.w;
        }
    }
    __half2 h01 = __floats2half2_rn(acc.x, acc.y);
    __half2 h23 = __floats2half2_rn(acc.z, acc.w);
    uint2 o = make_uint2(*(unsigned*)&h01, *(unsigned*)&h23);
    *(uint2*)(agg + (size_t)node * DIM + laneoff) = o;
}

// ---------------- fused 2-GEMM persistent kernel (fp16 MMA) ----------------
// z(fp16) = relu(A @ W1 + b1) @ W2 + b2, fused fp32 column stats.
// A fp16 in gmem; W1/W2 pre-packed half2 fragments; Tb fp16 in smem.
__global__ void __launch_bounds__(256, 1)
mlp_fused_tc(const __half* __restrict__ A,
             const unsigned* __restrict__ W1c,
             const unsigned* __restrict__ W2c,
             const float* __restrict__ b1,
             const float* __restrict__ b2,
             __half* __restrict__ C,
             int M,
             float* __restrict__ stats,
             int ntiles) {
    extern __shared__ unsigned smu[];
    unsigned* W1p = smu;                                  // 64 x 132 half2
    unsigned* W2p = smu + 64 * WPS;                       // 64 x 132 half2
    __half* Ab = (__half*)(smu + 2 * 64 * WPS);           // 64 x 136 halves
    __half* Tb = Ab + TILE_ROWS * AS_H;                   // 64 x 136 halves
    const int tid = threadIdx.x;
    const int warp = tid >> 5;
    const int lane = tid & 31;

    // load packed weights (64*128 uint each)
    for (int i = tid; i < 64 * DIM / 4; i += 256) {
        int r = i >> 5, c4 = (i & 31) * 4;
        uint4 v1 = *(const uint4*)(W1c + r * DIM + c4);
        uint4 v2 = *(const uint4*)(W2c + r * DIM + c4);
        unsigned* p1 = W1p + r * WPS + c4;
        unsigned* p2 = W2p + r * WPS + c4;
        p1[0] = v1.x; p1[1] = v1.y; p1[2] = v1.z; p1[3] = v1.w;
        p2[0] = v2.x; p2[1] = v2.y; p2[2] = v2.z; p2[3] = v2.w;
    }

    const int wm = (warp >> 2) * 32;
    const int wn = (warp & 3) * 32;
    const int lq = lane >> 2;
    const int lr = lane & 3;

    // prefetch first A tile: 64 rows x 256B = 1024 x 16B chunks
    int t = blockIdx.x;
    if (t < ntiles) {
        const __half* base = A + (size_t)t * TILE_ROWS * DIM;
        int maxrow = M - t * TILE_ROWS;
#pragma unroll
        for (int q = 0; q < 4; q++) {
            int idx = q * 256 + tid;
            int r = idx >> 4, c16 = (idx & 15) * 8;   // 8 halves = 16B
            unsigned saddr = (unsigned)__cvta_generic_to_shared(Ab + r * AS_H + c16);
            const __half* g = base + (r < maxrow ? r : 0) * DIM + c16;
            int sz = (r < maxrow) ? 16 : 0;
            asm volatile("cp.async.cg.shared.global [%0], [%1], 16, %2;"
                         :: "r"(saddr), "l"(g), "r"(sz));
        }
    }
    asm volatile("cp.async.commit_group;");

    for (; t < ntiles; t += GEMM_BLOCKS) {
        asm volatile("cp.async.wait_group 0;");
        __syncthreads();

        const int row0 = t * TILE_ROWS;

        // ---- mainloop 1: acc1 = A @ W1 (8 k16-steps) ----
        float acc1[2][4][4];
#pragma unroll
        for (int i = 0; i < 2; i++)
#pragma unroll
            for (int j = 0; j < 4; j++)
#pragma unroll
                for (int q = 0; q < 4; q++) acc1[i][j][q] = 0.f;

#pragma unroll
        for (int ks = 0; ks < 8; ks++) {
            const int k0 = ks * 16;
            unsigned af[2][4];
#pragma unroll
            for (int i = 0; i < 2; i++) {
                const __half* arow = Ab + (wm + i * 16 + lq) * AS_H + k0 + 2 * lr;
                af[i][0] = *(const unsigned*)arow;
                af[i][1] = *(const unsigned*)(arow + 8 * AS_H);
                af[i][2] = *(const unsigned*)(arow + 8);
                af[i][3] = *(const unsigned*)(arow + 8 * AS_H + 8);
            }
            unsigned bf[4][2];
#pragma unroll
            for (int j = 0; j < 4; j++) {
                const unsigned* bb = W1p + (ks * 8 + lr) * WPS + wn + j * 8 + lq;
                bf[j][0] = bb[0];
                bf[j][1] = bb[4 * WPS];
            }
#pragma unroll
            for (int i = 0; i < 2; i++)
#pragma unroll
                for (int j = 0; j < 4; j++) mma_f16(acc1[i][j], af[i], bf[j]);
        }
        __syncthreads();   // Ab reads done

        // prefetch next A tile (overlaps epilogue1 + mainloop2)
        int nxt = t + GEMM_BLOCKS;
        if (nxt < ntiles) {
            const __half* base = A + (size_t)nxt * TILE_ROWS * DIM;
            int maxrow = M - nxt * TILE_ROWS;
#pragma unroll
            for (int q = 0; q < 4; q++) {
                int idx = q * 256 + tid;
                int r = idx >> 4, c16 = (idx & 15) * 8;
                unsigned saddr = (unsigned)__cvta_generic_to_shared(Ab + r * AS_H + c16);
                const __half* g = base + (r < maxrow ? r : 0) * DIM + c16;
                int sz = (r < maxrow) ? 16 : 0;
                asm volatile("cp.async.cg.shared.global [%0], [%1], 16, %2;"
                             :: "r"(saddr), "l"(g), "r"(sz));
            }
        }
        asm volatile("cp.async.commit_group;");

        // ---- epilogue 1: T = fp16(relu(acc1 + b1)) into smem ----
#pragma unroll
        for (int i = 0; i < 2; i++) {
#pragma unroll
            for (int j = 0; j < 4; j++) {
                int col = wn + j * 8 + lr * 2;
                float c0 = b1[col], c1 = b1[col + 1];
                int rl = wm + i * 16 + lq;
                __half2 v0 = __floats2half2_rn(fmaxf(acc1[i][j][0] + c0, 0.f),
                                               fmaxf(acc1[i][j][1] + c1, 0.f));
                __half2 v1 = __floats2half2_rn(fmaxf(acc1[i][j][2] + c0, 0.f),
                                               fmaxf(acc1[i][j][3] + c1, 0.f));
                *(unsigned*)(Tb + rl * AS_H + col) = *(unsigned*)&v0;
                *(unsigned*)(Tb + (rl + 8) * AS_H + col) = *(unsigned*)&v1;
            }
        }
        __syncthreads();   // T ready

        // ---- mainloop 2: acc2 = T @ W2 ----
        float acc2[2][4][4];
#pragma unroll
        for (int i = 0; i < 2; i++)
#pragma unroll
            for (int j = 0; j < 4; j++)
#pragma unroll
                for (int q = 0; q < 4; q++) acc2[i][j][q] = 0.f;

#pragma unroll
        for (int ks = 0; ks < 8; ks++) {
            const int k0 = ks * 16;
            unsigned af[2][4];
#pragma unroll
            for (int i = 0; i < 2; i++) {
                const __half* arow = Tb + (wm + i * 16 + lq) * AS_H + k0 + 2 * lr;
                af[i][0] = *(const unsigned*)arow;
                af[i][1] = *(const unsigned*)(arow + 8 * AS_H);
                af[i][2] = *(const unsigned*)(arow + 8);
                af[i][3] = *(const unsigned*)(arow + 8 * AS_H + 8);
            }
            unsigned bf[4][2];
#pragma unroll
            for (int j = 0; j < 4; j++) {
                const unsigned* bb = W2p + (ks * 8 + lr) * WPS + wn + j * 8 + lq;
                bf[j][0] = bb[0];
                bf[j][1] = bb[4 * WPS];
            }
#pragma unroll
            for (int i = 0; i < 2; i++)
#pragma unroll
                for (int j = 0; j < 4; j++) mma_f16(acc2[i][j], af[i], bf[j]);
        }

        // ---- epilogue 2: z = fp16(acc2 + b2), store + fused fp32 stats ----
        float csum[8], csq[8];
#pragma unroll
        for (int k = 0; k < 8; k++) { csum[k] = 0.f; csq[k] = 0.f; }

#pragma unroll
        for (int i = 0; i < 2; i++) {
#pragma unroll
            for (int j = 0; j < 4; j++) {
                int col = wn + j * 8 + lr * 2;
                float c0 = b2[col], c1 = b2[col + 1];
                int r0 = row0 + wm + i * 16 + lq;
                float2 v0, v1;
                v0.x = acc2[i][j][0] + c0; v0.y = acc2[i][j][1] + c1;
                v1.x = acc2[i][j][2] + c0; v1.y = acc2[i][j][3] + c1;
                bool ok0 = r0 < M, ok1 = r0 + 8 < M;
                if (ok0) *(__half2*)(C + (size_t)r0 * DIM + col) = __floats2half2_rn(v0.x, v0.y);
                if (ok1) *(__half2*)(C + (size_t)(r0 + 8) * DIM + col) = __floats2half2_rn(v1.x, v1.y);
                csum[j * 2]     += (ok0 ? v0.x : 0.f) + (ok1 ? v1.x : 0.f);
                csum[j * 2 + 1] += (ok0 ? v0.y : 0.f) + (ok1 ? v1.y : 0.f);
                csq[j * 2]      += (ok0 ? v0.x * v0.x : 0.f) + (ok1 ? v1.x * v1.x : 0.f);
                csq[j * 2 + 1]  += (ok0 ? v0.y * v0.y : 0.f) + (ok1 ? v1.y * v1.y : 0.f);
            }
        }
#pragma unroll
        for (int k = 0; k < 8; k++) {
#pragma unroll
            for (int off = 4; off < 32; off <<= 1) {
                csum[k] += __shfl_xor_sync(0xffffffff, csum[k], off);
                csq[k]  += __shfl_xor_sync(0xffffffff, csq[k], off);
            }
        }
        if (lq == 0) {
#pragma unroll
            for (int k = 0; k < 8; k++) {
                int col = wn + (k >> 1) * 8 + lr * 2 + (k & 1);
                atomicAdd(&stats[col], csum[k]);
                atomicAdd(&stats[DIM + col], csq[k]);
            }
        }
        __syncthreads();   // Tb reads done before next tile rewrites it
    }
}

// ---------------- BatchNorm finalize ----------------
__global__ void bn_finalize(const float* __restrict__ stats,
                            const float* __restrict__ gamma,
                            const float* __restrict__ beta,
                            float* scale, float* shift) {
    int c = threadIdx.x;
    float mean = stats[c] / (float)N_NODES;
    float var = stats[DIM + c] / (float)N_NODES - mean * mean;
    float sc = gamma[c] * rsqrtf(var + BN_EPS);
    scale[c] = sc;
    shift[c] = beta[c] - mean * sc;
}

// ---------------- global_add_pool with fused bnrelu (fp16 z) ----------------
__global__ void pool_kernel(const __half* __restrict__ z,
                            const float* __restrict__ scale,
                            const float* __restrict__ shift,
                            const int* __restrict__ batch,
                            float* __restrict__ pool) {
    int node = (blockIdx.x * blockDim.x + threadIdx.x) >> 5;
    int lane = threadIdx.x & 31;
    if (node >= N_NODES) return;
    int b = batch[node];
    float4 v = ldh4(z + (size_t)node * DIM + lane * 4);
    float4 sc = *(const float4*)(scale + lane * 4);
    float4 sh = *(const float4*)(shift + lane * 4);
    v.x = fmaxf(fmaf(v.x, sc.x, sh.x), 0.f);
    v.y = fmaxf(fmaf(v.y, sc.y, sh.y), 0.f);
    v.z = fmaxf(fmaf(v.z, sc.z, sh.z), 0.f);
    v.w = fmaxf(fmaf(v.w, sc.w, sh.w), 0.f);
    float* p = pool + (size_t)b * DIM + lane * 4;
    asm volatile("red.global.add.v4.f32 [%0], {%1,%2,%3,%4};"
                 :: "l"(p), "f"(v.x), "f"(v.y), "f"(v.z), "f"(v.w) : "memory");
}

// ---------------- head MLP ----------------
__global__ void head_kernel(const float* __restrict__ pool,
                            const float* __restrict__ Wh1, const float* __restrict__ bh1,
                            const float* __restrict__ Wh2, const float* __restrict__ bh2,
                            float* __restrict__ out) {
    __shared__ float row[DIM];
    __shared__ float hid[DIM];
    int g = blockIdx.x;
    int t = threadIdx.x;
    row[t] = pool[(size_t)g * DIM + t];
    __syncthreads();
    float acc = bh1[t];
    for (int k = 0; k < DIM; k++) acc = fmaf(row[k], Wh1[k * DIM + t], acc);
    hid[t] = fmaxf(acc, 0.f);
    __syncthreads();
    if (t < OUT_DIM) {
        float o = bh2[t];
        for (int k = 0; k < DIM; k++) o = fmaf(hid[k], Wh2[k * OUT_DIM + t], o);
        out[(size_t)g * OUT_DIM + t] = o;
    }
}

// ---------------- launch ----------------
extern "C" void kernel_launch(void* const* d_in, const int* in_sizes, int n_in,
                              void* d_out, int out_size) {
    const float* x     = (const float*)d_in[0];
    const int*   ei    = (const int*)d_in[1];
    const int*   batch = (const int*)d_in[2];
    const float* W1s = (const float*)d_in[3];
    const float* b1s = (const float*)d_in[4];
    const float* W2s = (const float*)d_in[5];
    const float* b2s = (const float*)d_in[6];
    const float* gammas = (const float*)d_in[7];
    const float* betas  = (const float*)d_in[8];
    const float* Wh1 = (const float*)d_in[9];
    const float* bh1 = (const float*)d_in[10];
    const float* Wh2 = (const float*)d_in[11];
    const float* bh2 = (const float*)d_in[12];
    float* out = (float*)d_out;

    float *statsp, *scalep, *shiftp, *poolp;
    unsigned* wcp;
    __half *zp, *aggp;
    int* degp;
    cudaGetSymbolAddress((void**)&aggp, g_agg);
    cudaGetSymbolAddress((void**)&zp, g_z);
    cudaGetSymbolAddress((void**)&statsp, g_stats);
    cudaGetSymbolAddress((void**)&scalep, g_scale);
    cudaGetSymbolAddress((void**)&shiftp, g_shift);
    cudaGetSymbolAddress((void**)&poolp, g_pool);
    cudaGetSymbolAddress((void**)&wcp, g_wpack);
    cudaGetSymbolAddress((void**)&degp, g_deg);

    const int* src = ei;
    const int* dst = ei + N_EDGES;

    const int ntiles = (N_NODES + TILE_ROWS - 1) / TILE_ROWS;
    const int fusedSmem = (2 * 64 * WPS) * 4 + (2 * TILE_ROWS * AS_H) * 2;  // ~102 KB
    const int wPer = 64 * DIM;                 // packed uints per matrix per layer
    const int wPackTotal = N_LAYERS * wPer;
    const int edgeB = (N_EDGES + 255) / 256;
    const int aggBlocks = (N_NODES * 32 + 255) / 256;
    cudaFuncSetAttribute(mlp_fused_tc, cudaFuncAttributeMaxDynamicSharedMemorySize, fusedSmem);

    // ---- one-time per call: weight pack + stats zero + CSR build ----
    wpack_kernel<<<(wPackTotal + 255) / 256, 256>>>(W1s, W2s);
    zero_kernel<<<1, N_LAYERS * 2 * DIM / 4>>>(statsp, N_LAYERS * 2 * DIM / 4);
    zero_int_kernel<<<(N_NODES + 255) / 256, 256>>>(degp, N_NODES);
    count_kernel<<<edgeB, 256>>>(dst);
    scan_block_kernel<<<SCAN_NB, SCAN_B>>>();
    scan_totals_kernel<<<1, 32>>>();
    scan_add_kernel<<<SCAN_NB, SCAN_B>>>();
    fill_kernel<<<edgeB, 256>>>(src, dst);

    for (int l = 0; l < N_LAYERS; l++) {
        int raw = (l == 0) ? 1 : 0;
        float* lstats = statsp + (size_t)l * 2 * DIM;
        // agg = fp16(h + sum_neighbors h), h = bnrelu(z_prev) on the fly
        agg_kernel<<<aggBlocks, 256>>>(x, zp, scalep, shiftp, raw, aggp);
        // z = fp16(relu(agg @ W1 + b1) @ W2 + b2), fused stats
        mlp_fused_tc<<<GEMM_BLOCKS, 256, fusedSmem>>>(
            aggp,
            wcp + (size_t)l * wPer,
            wcp + (size_t)(N_LAYERS + l) * wPer,
            b1s + (size_t)l * DIM, b2s + (size_t)l * DIM,
            zp, N_NODES, lstats, ntiles);
        bn_finalize<<<1, DIM>>>(lstats, gammas + (size_t)l * DIM, betas + (size_t)l * DIM,
                                scalep, shiftp);
    }

    // global_add_pool of bnrelu(z_final)
    const int pool4 = N_GRAPHS * DIM / 4;
    zero_kernel<<<(pool4 + 255) / 256, 256>>>(poolp, pool4);
    pool_kernel<<<aggBlocks, 256>>>(zp, scalep, shiftp, batch, poolp);

    // head
    head_kernel<<<N_GRAPHS, DIM>>>(poolp, Wh1, bh1, Wh2, bh2, out);
}